// round 5
// baseline (speedup 1.0000x reference)
#include <cuda_runtime.h>
#include <cuda_bf16.h>
#include <cstdint>

#define NN 50000
#define NE 600000
#define DIM 128
#define KBIG 384
#define BN_EPS 1e-5f

typedef __nv_bfloat16 bf16;

// ============================ scratch globals ================================
__device__ int g_deg[NN];
__device__ int g_off[NN + 1];
__device__ int g_cursor[NN];
__device__ int g_eid[NE];
__device__ bf16 g_combh[NN * KBIG];
__device__ bf16 g_combl[NN * KBIG];
__device__ bf16 g_h0h[NN * DIM];
__device__ bf16 g_h0l[NN * DIM];
__device__ bf16 g_h1h[NN * DIM];
__device__ bf16 g_h1l[NN * DIM];
__device__ bf16 g_w0h[DIM * KBIG];
__device__ bf16 g_w0l[DIM * KBIG];
__device__ bf16 g_wf1h[DIM * DIM];
__device__ bf16 g_wf1l[DIM * DIM];
__device__ bf16 g_wf2h[DIM * DIM];
__device__ bf16 g_wf2l[DIM * DIM];
__device__ float g_bf1[DIM];
__device__ float g_bf2[DIM];
__device__ float g_stats[3 * 2 * DIM];
__device__ float g_a2c2[2 * DIM];
__device__ int g_is64;

__device__ __forceinline__ uint32_t pack2bf(float a, float b) {
    __nv_bfloat162 t = __floats2bfloat162_rn(a, b);
    return *reinterpret_cast<uint32_t*>(&t);
}

// ============================ small kernels ==================================
__global__ void detect_kernel(const int* __restrict__ ei32) {
    __shared__ int any;
    int t = threadIdx.x;
    if (t == 0) any = 0;
    __syncthreads();
    for (int i = t; i < 1024; i += blockDim.x)
        if (ei32[2 * i + 1] != 0) atomicOr(&any, 1);
    __syncthreads();
    if (t == 0) g_is64 = (any == 0) ? 1 : 0;
}

__device__ __forceinline__ int load_idx(const void* p, int i) {
    if (g_is64) return (int)((const long long*)p)[i];
    return ((const int*)p)[i];
}

__global__ void zero_kernel() {
    int i = blockIdx.x * blockDim.x + threadIdx.x;
    int stride = gridDim.x * blockDim.x;
    for (int j = i; j < NN; j += stride) g_deg[j] = 0;
    for (int j = i; j < 3 * 2 * DIM; j += stride) g_stats[j] = 0.f;
}

__global__ void hist_kernel(const void* __restrict__ ei, int nE, int n) {
    int e = blockIdx.x * blockDim.x + threadIdx.x;
    if (e >= nE) return;
    int src = load_idx(ei, e);
    if ((unsigned)src >= (unsigned)n) return;
    atomicAdd(&g_deg[src], 1);
}

// single-block shuffle-based exclusive scan of g_deg -> g_off / g_cursor
__global__ void scan_kernel(int n) {
    __shared__ int warpsum[32];
    __shared__ int carry;
    int tid = threadIdx.x;
    int lane = tid & 31;
    int wid = tid >> 5;
    if (tid == 0) carry = 0;
    __syncthreads();
    for (int base = 0; base < n; base += 1024) {
        int idx = base + tid;
        int v = (idx < n) ? g_deg[idx] : 0;
        int x = v;
#pragma unroll
        for (int off = 1; off < 32; off <<= 1) {
            int t = __shfl_up_sync(0xffffffffu, x, off);
            if (lane >= off) x += t;
        }
        if (lane == 31) warpsum[wid] = x;
        __syncthreads();
        if (wid == 0) {
            int w = warpsum[lane];
            int y = w;
#pragma unroll
            for (int off = 1; off < 32; off <<= 1) {
                int t = __shfl_up_sync(0xffffffffu, y, off);
                if (lane >= off) y += t;
            }
            warpsum[lane] = y - w;  // exclusive
        }
        __syncthreads();
        int excl = x - v + warpsum[wid] + carry;
        if (idx < n) {
            g_off[idx] = excl;
            g_cursor[idx] = excl;
        }
        __syncthreads();
        if (tid == 1023) carry += x + warpsum[wid];
        __syncthreads();
    }
    if (tid == 0) g_off[n] = carry;
}

__global__ void fill_kernel(const void* __restrict__ ei, int nE, int n) {
    int e = blockIdx.x * blockDim.x + threadIdx.x;
    if (e >= nE) return;
    int src = load_idx(ei, e);
    if ((unsigned)src >= (unsigned)n) return;
    int pos = atomicAdd(&g_cursor[src], 1);
    g_eid[pos] = e;
}

__device__ __forceinline__ void split4(float4 v, uint2& H, uint2& L) {
    bf16 h0 = __float2bfloat16_rn(v.x);
    bf16 h1 = __float2bfloat16_rn(v.y);
    bf16 h2 = __float2bfloat16_rn(v.z);
    bf16 h3 = __float2bfloat16_rn(v.w);
    float l0 = v.x - __bfloat162float(h0);
    float l1 = v.y - __bfloat162float(h1);
    float l2 = v.z - __bfloat162float(h2);
    float l3 = v.w - __bfloat162float(h3);
    __nv_bfloat162 p01; p01.x = h0; p01.y = h1;
    __nv_bfloat162 p23; p23.x = h2; p23.y = h3;
    H.x = *reinterpret_cast<uint32_t*>(&p01);
    H.y = *reinterpret_cast<uint32_t*>(&p23);
    L.x = pack2bf(l0, l1);
    L.y = pack2bf(l2, l3);
}

// one warp per node: gather-sum incident edges, build split-bf16 comb rows
__global__ void gather_comb_kernel(const float* __restrict__ ea,
                                   const float* __restrict__ x,
                                   const float* __restrict__ u,
                                   const void* __restrict__ batch,
                                   int n, int nG) {
    int t = blockIdx.x * blockDim.x + threadIdx.x;
    int node = t >> 5;
    int lane = t & 31;
    if (node >= n) return;
    int beg = g_off[node];
    int end = g_off[node + 1];

    const float4* ea4 = reinterpret_cast<const float4*>(ea);
    float4 acc = make_float4(0.f, 0.f, 0.f, 0.f);
    for (int i = beg; i < end; i++) {
        int eid = g_eid[i];
        float4 v = ea4[(size_t)eid * 32 + lane];
        acc.x += v.x; acc.y += v.y; acc.z += v.z; acc.w += v.w;
    }
    float inv = 1.f / fmaxf((float)(end - beg), 1.f);
    acc.x *= inv; acc.y *= inv; acc.z *= inv; acc.w *= inv;

    int b = load_idx(batch, node);
    if ((unsigned)b >= (unsigned)nG) b = 0;
    float4 xv = reinterpret_cast<const float4*>(x)[(size_t)node * 32 + lane];
    float4 uv = reinterpret_cast<const float4*>(u)[(size_t)b * 32 + lane];

    uint2* ch = reinterpret_cast<uint2*>(g_combh);
    uint2* cl = reinterpret_cast<uint2*>(g_combl);
    size_t base = (size_t)node * 96;
    uint2 H, L;
    split4(xv, H, L);  ch[base + lane] = H;      cl[base + lane] = L;
    split4(acc, H, L); ch[base + 32 + lane] = H; cl[base + 32 + lane] = L;
    split4(uv, H, L);  ch[base + 64 + lane] = H; cl[base + 64 + lane] = L;
}

__global__ void w0split_kernel(const float* __restrict__ W0) {
    int i = blockIdx.x * blockDim.x + threadIdx.x;
    if (i >= DIM * KBIG) return;
    float w = W0[i];
    bf16 h = __float2bfloat16_rn(w);
    g_w0h[i] = h;
    g_w0l[i] = __float2bfloat16_rn(w - __bfloat162float(h));
}

__global__ void fold_kernel(const float* __restrict__ stats,
                            const float* __restrict__ gamma,
                            const float* __restrict__ beta,
                            const float* __restrict__ Wn,
                            const float* __restrict__ bn,
                            bf16* __restrict__ Wh, bf16* __restrict__ Wl,
                            float* __restrict__ bf, float n) {
    __shared__ float a[128], c[128];
    int tid = threadIdx.x;
    float m = stats[tid] / n;
    float var = stats[128 + tid] / n - m * m;
    float rs = rsqrtf(var + BN_EPS);
    a[tid] = gamma[tid] * rs;
    c[tid] = beta[tid] - gamma[tid] * m * rs;
    __syncthreads();
    float accb = 0.f;
#pragma unroll 4
    for (int k = 0; k < 128; k++) {
        float w = Wn[tid * 128 + k];
        float wf = w * a[k];
        bf16 h = __float2bfloat16_rn(wf);
        Wh[tid * 128 + k] = h;
        Wl[tid * 128 + k] = __float2bfloat16_rn(wf - __bfloat162float(h));
        accb += c[k] * w;
    }
    bf[tid] = bn[tid] + accb;
}

__global__ void finalfold_kernel(const float* __restrict__ stats,
                                 const float* __restrict__ gamma,
                                 const float* __restrict__ beta, float n) {
    int tid = threadIdx.x;
    float m = stats[tid] / n;
    float var = stats[128 + tid] / n - m * m;
    float rs = rsqrtf(var + BN_EPS);
    g_a2c2[tid] = gamma[tid] * rs;
    g_a2c2[128 + tid] = beta[tid] - gamma[tid] * m * rs;
}

__global__ void norm_kernel(float* __restrict__ out, int n) {
    int i = blockIdx.x * blockDim.x + threadIdx.x;
    int stride = gridDim.x * blockDim.x;
    float4* o4 = reinterpret_cast<float4*>(out);
    const float4* a4 = reinterpret_cast<const float4*>(g_a2c2);
    const float4* c4 = reinterpret_cast<const float4*>(g_a2c2 + 128);
    for (int j = i; j < n * 32; j += stride) {
        int q = j & 31;
        float4 v = o4[j];
        float4 a = a4[q];
        float4 c = c4[q];
        v.x = v.x * a.x + c.x;
        v.y = v.y * a.y + c.y;
        v.z = v.z * a.z + c.z;
        v.w = v.w * a.w + c.w;
        o4[j] = v;
    }
}

// ====================== mma.sync bf16-split GEMM =============================
__device__ __forceinline__ void mma16816(float* c, const uint32_t* a,
                                         uint32_t b0, uint32_t b1) {
    asm volatile(
        "mma.sync.aligned.m16n8k16.row.col.f32.bf16.bf16.f32 "
        "{%0,%1,%2,%3}, {%4,%5,%6,%7}, {%8,%9}, {%0,%1,%2,%3};"
        : "+f"(c[0]), "+f"(c[1]), "+f"(c[2]), "+f"(c[3])
        : "r"(a[0]), "r"(a[1]), "r"(a[2]), "r"(a[3]), "r"(b0), "r"(b1));
}

static constexpr int LDSTR = 72;  // padded smem row stride (bf16 elems)
static constexpr int TILE_ELEMS = 128 * LDSTR;
static constexpr int GEMM_SMEM = 4 * TILE_ELEMS * 2 + 3 * 128 * 4;

template <int K, bool LAST>
__global__ void __launch_bounds__(256)
gemm_mma(const bf16* __restrict__ Ah, const bf16* __restrict__ Al,
         const bf16* __restrict__ Wh, const bf16* __restrict__ Wl,
         const float* __restrict__ bias, float* __restrict__ outF,
         bf16* __restrict__ Ch, bf16* __restrict__ Cl,
         float* __restrict__ stats, int n) {
    extern __shared__ __align__(16) char dsm[];
    bf16* sAh = reinterpret_cast<bf16*>(dsm);
    bf16* sAl = sAh + TILE_ELEMS;
    bf16* sWh = sAl + TILE_ELEMS;
    bf16* sWl = sWh + TILE_ELEMS;
    float* red0 = reinterpret_cast<float*>(dsm + 4 * TILE_ELEMS * 2);
    float* red1 = red0 + 128;
    float* sbias = red1 + 128;

    const int tid = threadIdx.x;
    const int wid = tid >> 5;
    const int lane = tid & 31;
    const int warp_m = wid & 3;
    const int warp_n = wid >> 2;
    const int groupID = lane >> 2;
    const int tig = lane & 3;
    const int rowBase = blockIdx.x * 128;

    if (tid < 128) {
        red0[tid] = 0.f;
        red1[tid] = 0.f;
        sbias[tid] = bias[tid];
    }

    float acc[2][8][4];
#pragma unroll
    for (int mt = 0; mt < 2; mt++)
#pragma unroll
        for (int nt = 0; nt < 8; nt++)
#pragma unroll
            for (int q = 0; q < 4; q++) acc[mt][nt][q] = 0.f;

    const int lrow = tid >> 1;
    const int lhalf = (tid & 1) * 32;
    const bool rowOK = (rowBase + lrow) < n;

#pragma unroll 1
    for (int c = 0; c < K / 64; c++) {
        const int k0 = c * 64;
        if (c > 0) __syncthreads();
        {
            const uint4* pAh = reinterpret_cast<const uint4*>(
                Ah + (size_t)(rowBase + lrow) * K + k0 + lhalf);
            const uint4* pAl = reinterpret_cast<const uint4*>(
                Al + (size_t)(rowBase + lrow) * K + k0 + lhalf);
            const uint4* pWh = reinterpret_cast<const uint4*>(
                Wh + (size_t)lrow * K + k0 + lhalf);
            const uint4* pWl = reinterpret_cast<const uint4*>(
                Wl + (size_t)lrow * K + k0 + lhalf);
            uint4 z = make_uint4(0, 0, 0, 0);
#pragma unroll
            for (int i = 0; i < 4; i++) {
                uint4 vh = rowOK ? pAh[i] : z;
                uint4 vl = rowOK ? pAl[i] : z;
                uint4 wh = pWh[i];
                uint4 wl = pWl[i];
                int off = lrow * LDSTR + lhalf + i * 8;
                *reinterpret_cast<uint4*>(sAh + off) = vh;
                *reinterpret_cast<uint4*>(sAl + off) = vl;
                *reinterpret_cast<uint4*>(sWh + off) = wh;
                *reinterpret_cast<uint4*>(sWl + off) = wl;
            }
        }
        __syncthreads();

#pragma unroll
        for (int kk = 0; kk < 4; kk++) {
            const int ac = kk * 16 + tig * 2;
            uint32_t aH[2][4], aL[2][4];
#pragma unroll
            for (int mt = 0; mt < 2; mt++) {
                int r = warp_m * 32 + mt * 16 + groupID;
                const bf16* pH = sAh + r * LDSTR + ac;
                const bf16* pL = sAl + r * LDSTR + ac;
                aH[mt][0] = *reinterpret_cast<const uint32_t*>(pH);
                aH[mt][1] = *reinterpret_cast<const uint32_t*>(pH + 8 * LDSTR);
                aH[mt][2] = *reinterpret_cast<const uint32_t*>(pH + 8);
                aH[mt][3] = *reinterpret_cast<const uint32_t*>(pH + 8 * LDSTR + 8);
                aL[mt][0] = *reinterpret_cast<const uint32_t*>(pL);
                aL[mt][1] = *reinterpret_cast<const uint32_t*>(pL + 8 * LDSTR);
                aL[mt][2] = *reinterpret_cast<const uint32_t*>(pL + 8);
                aL[mt][3] = *reinterpret_cast<const uint32_t*>(pL + 8 * LDSTR + 8);
            }
#pragma unroll
            for (int nt = 0; nt < 8; nt++) {
                int wr = warp_n * 64 + nt * 8 + groupID;
                const bf16* qH = sWh + wr * LDSTR + ac;
                const bf16* qL = sWl + wr * LDSTR + ac;
                uint32_t bH0 = *reinterpret_cast<const uint32_t*>(qH);
                uint32_t bH1 = *reinterpret_cast<const uint32_t*>(qH + 8);
                uint32_t bL0 = *reinterpret_cast<const uint32_t*>(qL);
                uint32_t bL1 = *reinterpret_cast<const uint32_t*>(qL + 8);
#pragma unroll
                for (int mt = 0; mt < 2; mt++) {
                    mma16816(acc[mt][nt], aH[mt], bH0, bH1);
                    mma16816(acc[mt][nt], aL[mt], bH0, bH1);
                    mma16816(acc[mt][nt], aH[mt], bL0, bL1);
                }
            }
        }
    }

    // ---------------- epilogue: bias + relu + stats + store ----------------
#pragma unroll
    for (int mt = 0; mt < 2; mt++) {
        int r0 = rowBase + warp_m * 32 + mt * 16 + groupID;
        int r1 = r0 + 8;
#pragma unroll
        for (int nt = 0; nt < 8; nt++) {
            int j = warp_n * 64 + nt * 8 + tig * 2;
            float* a = acc[mt][nt];
            float b0v = sbias[j], b1v = sbias[j + 1];
            float v0 = (r0 < n) ? fmaxf(a[0] + b0v, 0.f) : 0.f;
            float v1 = (r0 < n) ? fmaxf(a[1] + b1v, 0.f) : 0.f;
            float v2 = (r1 < n) ? fmaxf(a[2] + b0v, 0.f) : 0.f;
            float v3 = (r1 < n) ? fmaxf(a[3] + b1v, 0.f) : 0.f;

            float s0 = v0 + v2, s1 = v1 + v3;
            float q0 = v0 * v0 + v2 * v2, q1 = v1 * v1 + v3 * v3;
#pragma unroll
            for (int off = 4; off < 32; off <<= 1) {
                s0 += __shfl_xor_sync(0xffffffffu, s0, off);
                s1 += __shfl_xor_sync(0xffffffffu, s1, off);
                q0 += __shfl_xor_sync(0xffffffffu, q0, off);
                q1 += __shfl_xor_sync(0xffffffffu, q1, off);
            }
            if (groupID == 0) {
                atomicAdd(red0 + j, s0);
                atomicAdd(red0 + j + 1, s1);
                atomicAdd(red1 + j, q0);
                atomicAdd(red1 + j + 1, q1);
            }

            if (LAST) {
                if (r0 < n)
                    *reinterpret_cast<float2*>(outF + (size_t)r0 * 128 + j) =
                        make_float2(v0, v1);
                if (r1 < n)
                    *reinterpret_cast<float2*>(outF + (size_t)r1 * 128 + j) =
                        make_float2(v2, v3);
            } else {
                if (r0 < n) {
                    bf16 h0 = __float2bfloat16_rn(v0);
                    bf16 h1 = __float2bfloat16_rn(v1);
                    __nv_bfloat162 hp; hp.x = h0; hp.y = h1;
                    *reinterpret_cast<uint32_t*>(Ch + (size_t)r0 * 128 + j) =
                        *reinterpret_cast<uint32_t*>(&hp);
                    *reinterpret_cast<uint32_t*>(Cl + (size_t)r0 * 128 + j) =
                        pack2bf(v0 - __bfloat162float(h0), v1 - __bfloat162float(h1));
                }
                if (r1 < n) {
                    bf16 h2 = __float2bfloat16_rn(v2);
                    bf16 h3 = __float2bfloat16_rn(v3);
                    __nv_bfloat162 hp; hp.x = h2; hp.y = h3;
                    *reinterpret_cast<uint32_t*>(Ch + (size_t)r1 * 128 + j) =
                        *reinterpret_cast<uint32_t*>(&hp);
                    *reinterpret_cast<uint32_t*>(Cl + (size_t)r1 * 128 + j) =
                        pack2bf(v2 - __bfloat162float(h2), v3 - __bfloat162float(h3));
                }
            }
        }
    }
    __syncthreads();
    if (tid < 128) {
        atomicAdd(&stats[tid], red0[tid]);
        atomicAdd(&stats[128 + tid], red1[tid]);
    }
}

// ============================ host launcher ==================================
extern "C" void kernel_launch(void* const* d_in, const int* in_sizes, int n_in,
                              void* d_out, int out_size) {
    const float* x = (const float*)d_in[0];
    const void* ei = d_in[1];
    const float* ea = (const float*)d_in[2];
    const float* u = (const float*)d_in[3];
    const void* batch = d_in[4];
    const float* W0 = (const float*)d_in[5];
    const float* b0 = (const float*)d_in[6];
    const float* W1 = (const float*)d_in[7];
    const float* b1 = (const float*)d_in[8];
    const float* W2 = (const float*)d_in[9];
    const float* b2 = (const float*)d_in[10];
    const float* g0 = (const float*)d_in[11];
    const float* be0 = (const float*)d_in[12];
    const float* g1 = (const float*)d_in[13];
    const float* be1 = (const float*)d_in[14];
    const float* g2 = (const float*)d_in[15];
    const float* be2 = (const float*)d_in[16];

    int n = in_sizes[0] / DIM;
    int nE = in_sizes[2] / DIM;
    int nG = in_sizes[3] / DIM;
    float* out = (float*)d_out;

    bf16 *combh, *combl, *h0h, *h0l, *h1h, *h1l;
    bf16 *w0h, *w0l, *wf1h, *wf1l, *wf2h, *wf2l;
    float *stats, *bf1, *bf2;
    cudaGetSymbolAddress((void**)&combh, g_combh);
    cudaGetSymbolAddress((void**)&combl, g_combl);
    cudaGetSymbolAddress((void**)&h0h, g_h0h);
    cudaGetSymbolAddress((void**)&h0l, g_h0l);
    cudaGetSymbolAddress((void**)&h1h, g_h1h);
    cudaGetSymbolAddress((void**)&h1l, g_h1l);
    cudaGetSymbolAddress((void**)&w0h, g_w0h);
    cudaGetSymbolAddress((void**)&w0l, g_w0l);
    cudaGetSymbolAddress((void**)&wf1h, g_wf1h);
    cudaGetSymbolAddress((void**)&wf1l, g_wf1l);
    cudaGetSymbolAddress((void**)&wf2h, g_wf2h);
    cudaGetSymbolAddress((void**)&wf2l, g_wf2l);
    cudaGetSymbolAddress((void**)&stats, g_stats);
    cudaGetSymbolAddress((void**)&bf1, g_bf1);
    cudaGetSymbolAddress((void**)&bf2, g_bf2);

    cudaFuncSetAttribute(gemm_mma<KBIG, false>,
                         cudaFuncAttributeMaxDynamicSharedMemorySize, GEMM_SMEM);
    cudaFuncSetAttribute(gemm_mma<DIM, false>,
                         cudaFuncAttributeMaxDynamicSharedMemorySize, GEMM_SMEM);
    cudaFuncSetAttribute(gemm_mma<DIM, true>,
                         cudaFuncAttributeMaxDynamicSharedMemorySize, GEMM_SMEM);

    detect_kernel<<<1, 256>>>((const int*)ei);
    zero_kernel<<<512, 256>>>();
    hist_kernel<<<(nE + 255) / 256, 256>>>(ei, nE, n);
    scan_kernel<<<1, 1024>>>(n);
    fill_kernel<<<(nE + 255) / 256, 256>>>(ei, nE, n);
    gather_comb_kernel<<<(n * 32 + 255) / 256, 256>>>(ea, x, u, batch, n, nG);
    w0split_kernel<<<(DIM * KBIG + 255) / 256, 256>>>(W0);

    int gblocks = (n + 127) / 128;
    gemm_mma<KBIG, false><<<gblocks, 256, GEMM_SMEM>>>(
        combh, combl, w0h, w0l, b0, nullptr, h0h, h0l, stats, n);
    fold_kernel<<<1, 128>>>(stats, g0, be0, W1, b1, wf1h, wf1l, bf1, (float)n);
    gemm_mma<DIM, false><<<gblocks, 256, GEMM_SMEM>>>(
        h0h, h0l, wf1h, wf1l, bf1, nullptr, h1h, h1l, stats + 256, n);
    fold_kernel<<<1, 128>>>(stats + 256, g1, be1, W2, b2, wf2h, wf2l, bf2, (float)n);
    gemm_mma<DIM, true><<<gblocks, 256, GEMM_SMEM>>>(
        h1h, h1l, wf2h, wf2l, bf2, out, nullptr, nullptr, stats + 512, n);
    finalfold_kernel<<<1, 128>>>(stats + 512, g2, be2, (float)n);
    norm_kernel<<<1024, 256>>>(out, n);
}

// round 6
// speedup vs baseline: 1.0347x; 1.0347x over previous
#include <cuda_runtime.h>
#include <cuda_bf16.h>
#include <cstdint>

#define NN 50000
#define NE 600000
#define DIM 128
#define KBIG 384
#define BN_EPS 1e-5f

typedef __nv_bfloat16 bf16;

// ============================ scratch globals ================================
__device__ int g_deg[NN];
__device__ int g_off[NN + 1];
__device__ int g_cursor[NN];
__device__ int g_eid[NE];
__device__ int g_bsum[64];
__device__ bf16 g_combh[NN * KBIG];
__device__ bf16 g_combl[NN * KBIG];
__device__ bf16 g_h0h[NN * DIM];
__device__ bf16 g_h0l[NN * DIM];
__device__ bf16 g_h1h[NN * DIM];
__device__ bf16 g_h1l[NN * DIM];
__device__ bf16 g_w0h[DIM * KBIG];
__device__ bf16 g_w0l[DIM * KBIG];
__device__ bf16 g_wf1h[DIM * DIM];
__device__ bf16 g_wf1l[DIM * DIM];
__device__ bf16 g_wf2h[DIM * DIM];
__device__ bf16 g_wf2l[DIM * DIM];
__device__ float g_bf1[DIM];
__device__ float g_bf2[DIM];
__device__ float g_stats[3 * 2 * DIM];
__device__ float g_a2c2[2 * DIM];
__device__ int g_is64;

__device__ __forceinline__ uint32_t pack2bf(float a, float b) {
    __nv_bfloat162 t = __floats2bfloat162_rn(a, b);
    return *reinterpret_cast<uint32_t*>(&t);
}

__device__ __forceinline__ uint32_t smem_u32(const void* p) {
    uint32_t a;
    asm("{ .reg .u64 t; cvta.to.shared.u64 t, %1; cvt.u32.u64 %0, t; }"
        : "=r"(a) : "l"(p));
    return a;
}

#define CP_ASYNC16(dst, src, sz) \
    asm volatile("cp.async.ca.shared.global [%0], [%1], 16, %2;" \
                 :: "r"(dst), "l"(src), "r"(sz))
#define CP_COMMIT() asm volatile("cp.async.commit_group;" ::: "memory")
#define CP_WAIT0() asm volatile("cp.async.wait_group 0;" ::: "memory")
#define CP_WAIT1() asm volatile("cp.async.wait_group 1;" ::: "memory")

// ============================ small kernels ==================================
__global__ void detect_kernel(const int* __restrict__ ei32) {
    __shared__ int any;
    int t = threadIdx.x;
    if (t == 0) any = 0;
    __syncthreads();
    for (int i = t; i < 1024; i += blockDim.x)
        if (ei32[2 * i + 1] != 0) atomicOr(&any, 1);
    __syncthreads();
    if (t == 0) g_is64 = (any == 0) ? 1 : 0;
}

__device__ __forceinline__ int load_idx(const void* p, int i) {
    if (g_is64) return (int)((const long long*)p)[i];
    return ((const int*)p)[i];
}

__global__ void zero_kernel() {
    int i = blockIdx.x * blockDim.x + threadIdx.x;
    int stride = gridDim.x * blockDim.x;
    for (int j = i; j < NN; j += stride) g_deg[j] = 0;
    for (int j = i; j < 3 * 2 * DIM; j += stride) g_stats[j] = 0.f;
}

__global__ void hist_kernel(const void* __restrict__ ei, int nE, int n) {
    int e = blockIdx.x * blockDim.x + threadIdx.x;
    if (e >= nE) return;
    int src = load_idx(ei, e);
    if ((unsigned)src >= (unsigned)n) return;
    atomicAdd(&g_deg[src], 1);
}

// ---------- 3-phase parallel exclusive scan of g_deg -> g_off/g_cursor -------
__global__ void scan1_kernel(int n) {
    __shared__ int wsum[32];
    int tid = threadIdx.x;
    int lane = tid & 31;
    int wid = tid >> 5;
    int idx = blockIdx.x * 1024 + tid;
    int v = (idx < n) ? g_deg[idx] : 0;
    int x = v;
#pragma unroll
    for (int off = 1; off < 32; off <<= 1) {
        int t = __shfl_up_sync(0xffffffffu, x, off);
        if (lane >= off) x += t;
    }
    if (lane == 31) wsum[wid] = x;
    __syncthreads();
    if (wid == 0) {
        int w = wsum[lane];
        int y = w;
#pragma unroll
        for (int off = 1; off < 32; off <<= 1) {
            int t = __shfl_up_sync(0xffffffffu, y, off);
            if (lane >= off) y += t;
        }
        wsum[lane] = y - w;  // exclusive warp offsets
    }
    __syncthreads();
    int excl = x - v + wsum[wid];
    if (idx < n) g_off[idx] = excl;
    if (tid == 1023) g_bsum[blockIdx.x] = excl + v;  // block total
}

__global__ void scan2_kernel(int nb, int n) {
    if (threadIdx.x == 0) {
        int run = 0;
        for (int i = 0; i < nb; i++) {
            int t = g_bsum[i];
            g_bsum[i] = run;
            run += t;
        }
        g_off[n] = run;
    }
}

__global__ void scan3_kernel(int n) {
    int idx = blockIdx.x * 1024 + threadIdx.x;
    if (idx < n) {
        int o = g_off[idx] + g_bsum[blockIdx.x];
        g_off[idx] = o;
        g_cursor[idx] = o;
    }
}

__global__ void fill_kernel(const void* __restrict__ ei, int nE, int n) {
    int e = blockIdx.x * blockDim.x + threadIdx.x;
    if (e >= nE) return;
    int src = load_idx(ei, e);
    if ((unsigned)src >= (unsigned)n) return;
    int pos = atomicAdd(&g_cursor[src], 1);
    g_eid[pos] = e;
}

__device__ __forceinline__ void split4(float4 v, uint2& H, uint2& L) {
    bf16 h0 = __float2bfloat16_rn(v.x);
    bf16 h1 = __float2bfloat16_rn(v.y);
    bf16 h2 = __float2bfloat16_rn(v.z);
    bf16 h3 = __float2bfloat16_rn(v.w);
    float l0 = v.x - __bfloat162float(h0);
    float l1 = v.y - __bfloat162float(h1);
    float l2 = v.z - __bfloat162float(h2);
    float l3 = v.w - __bfloat162float(h3);
    __nv_bfloat162 p01; p01.x = h0; p01.y = h1;
    __nv_bfloat162 p23; p23.x = h2; p23.y = h3;
    H.x = *reinterpret_cast<uint32_t*>(&p01);
    H.y = *reinterpret_cast<uint32_t*>(&p23);
    L.x = pack2bf(l0, l1);
    L.y = pack2bf(l2, l3);
}

// one warp per node: gather-sum incident edges, build split-bf16 comb rows
__global__ void gather_comb_kernel(const float* __restrict__ ea,
                                   const float* __restrict__ x,
                                   const float* __restrict__ u,
                                   const void* __restrict__ batch,
                                   int n, int nG) {
    int t = blockIdx.x * blockDim.x + threadIdx.x;
    int node = t >> 5;
    int lane = t & 31;
    if (node >= n) return;
    int beg = g_off[node];
    int end = g_off[node + 1];

    const float4* ea4 = reinterpret_cast<const float4*>(ea);
    float4 acc = make_float4(0.f, 0.f, 0.f, 0.f);
    for (int i = beg; i < end; i++) {
        int eid = g_eid[i];
        float4 v = ea4[(size_t)eid * 32 + lane];
        acc.x += v.x; acc.y += v.y; acc.z += v.z; acc.w += v.w;
    }
    float inv = 1.f / fmaxf((float)(end - beg), 1.f);
    acc.x *= inv; acc.y *= inv; acc.z *= inv; acc.w *= inv;

    int b = load_idx(batch, node);
    if ((unsigned)b >= (unsigned)nG) b = 0;
    float4 xv = reinterpret_cast<const float4*>(x)[(size_t)node * 32 + lane];
    float4 uv = reinterpret_cast<const float4*>(u)[(size_t)b * 32 + lane];

    uint2* ch = reinterpret_cast<uint2*>(g_combh);
    uint2* cl = reinterpret_cast<uint2*>(g_combl);
    size_t base = (size_t)node * 96;
    uint2 H, L;
    split4(xv, H, L);  ch[base + lane] = H;      cl[base + lane] = L;
    split4(acc, H, L); ch[base + 32 + lane] = H; cl[base + 32 + lane] = L;
    split4(uv, H, L);  ch[base + 64 + lane] = H; cl[base + 64 + lane] = L;
}

__global__ void w0split_kernel(const float* __restrict__ W0) {
    int i = blockIdx.x * blockDim.x + threadIdx.x;
    if (i >= DIM * KBIG) return;
    float w = W0[i];
    bf16 h = __float2bfloat16_rn(w);
    g_w0h[i] = h;
    g_w0l[i] = __float2bfloat16_rn(w - __bfloat162float(h));
}

__global__ void fold_kernel(const float* __restrict__ stats,
                            const float* __restrict__ gamma,
                            const float* __restrict__ beta,
                            const float* __restrict__ Wn,
                            const float* __restrict__ bn,
                            bf16* __restrict__ Wh, bf16* __restrict__ Wl,
                            float* __restrict__ bf, float n) {
    __shared__ float a[128], c[128];
    int tid = threadIdx.x;
    float m = stats[tid] / n;
    float var = stats[128 + tid] / n - m * m;
    float rs = rsqrtf(var + BN_EPS);
    a[tid] = gamma[tid] * rs;
    c[tid] = beta[tid] - gamma[tid] * m * rs;
    __syncthreads();
    float accb = 0.f;
#pragma unroll 4
    for (int k = 0; k < 128; k++) {
        float w = Wn[tid * 128 + k];
        float wf = w * a[k];
        bf16 h = __float2bfloat16_rn(wf);
        Wh[tid * 128 + k] = h;
        Wl[tid * 128 + k] = __float2bfloat16_rn(wf - __bfloat162float(h));
        accb += c[k] * w;
    }
    bf[tid] = bn[tid] + accb;
}

__global__ void finalfold_kernel(const float* __restrict__ stats,
                                 const float* __restrict__ gamma,
                                 const float* __restrict__ beta, float n) {
    int tid = threadIdx.x;
    float m = stats[tid] / n;
    float var = stats[128 + tid] / n - m * m;
    float rs = rsqrtf(var + BN_EPS);
    g_a2c2[tid] = gamma[tid] * rs;
    g_a2c2[128 + tid] = beta[tid] - gamma[tid] * m * rs;
}

__global__ void norm_kernel(float* __restrict__ out, int n) {
    int i = blockIdx.x * blockDim.x + threadIdx.x;
    int stride = gridDim.x * blockDim.x;
    float4* o4 = reinterpret_cast<float4*>(out);
    const float4* a4 = reinterpret_cast<const float4*>(g_a2c2);
    const float4* c4 = reinterpret_cast<const float4*>(g_a2c2 + 128);
    for (int j = i; j < n * 32; j += stride) {
        int q = j & 31;
        float4 v = o4[j];
        float4 a = a4[q];
        float4 c = c4[q];
        v.x = v.x * a.x + c.x;
        v.y = v.y * a.y + c.y;
        v.z = v.z * a.z + c.z;
        v.w = v.w * a.w + c.w;
        o4[j] = v;
    }
}

// ====================== mma.sync bf16-split GEMM (cp.async 2-stage) ==========
__device__ __forceinline__ void mma16816(float* c, const uint32_t* a,
                                         uint32_t b0, uint32_t b1) {
    asm volatile(
        "mma.sync.aligned.m16n8k16.row.col.f32.bf16.bf16.f32 "
        "{%0,%1,%2,%3}, {%4,%5,%6,%7}, {%8,%9}, {%0,%1,%2,%3};"
        : "+f"(c[0]), "+f"(c[1]), "+f"(c[2]), "+f"(c[3])
        : "r"(a[0]), "r"(a[1]), "r"(a[2]), "r"(a[3]), "r"(b0), "r"(b1));
}

static constexpr int LDSTR = 72;                       // bf16 elems per smem row
static constexpr int TILE_ELEMS = 128 * LDSTR;         // 9216
static constexpr int TILE_B = TILE_ELEMS * 2;          // 18432 bytes
static constexpr int STAGE_B = 4 * TILE_B;             // 73728 bytes
static constexpr int GEMM_SMEM = 2 * STAGE_B + 3 * 128 * 4;

template <int K, bool LAST>
__global__ void __launch_bounds__(256)
gemm_mma(const bf16* __restrict__ Ah, const bf16* __restrict__ Al,
         const bf16* __restrict__ Wh, const bf16* __restrict__ Wl,
         const float* __restrict__ bias, float* __restrict__ outF,
         bf16* __restrict__ Ch, bf16* __restrict__ Cl,
         float* __restrict__ stats, int n) {
    extern __shared__ __align__(16) char dsm[];
    float* red0 = reinterpret_cast<float*>(dsm + 2 * STAGE_B);
    float* red1 = red0 + 128;
    float* sbias = red1 + 128;

    const int tid = threadIdx.x;
    const int wid = tid >> 5;
    const int lane = tid & 31;
    const int warp_m = wid & 3;
    const int warp_n = wid >> 2;
    const int groupID = lane >> 2;
    const int tig = lane & 3;
    const int rowBase = blockIdx.x * 128;

    const int lrow = tid >> 1;
    const int lhalf = (tid & 1) * 32;
    const bool rowOK = (rowBase + lrow) < n;
    const int arow = rowOK ? (rowBase + lrow) : (n - 1);  // clamp address
    const uint32_t aSz = rowOK ? 16u : 0u;                // zero-fill OOB

    const uint32_t sb = smem_u32(dsm);
    const uint32_t rowoff = (uint32_t)(lrow * LDSTR + lhalf) * 2;

    const char* gAh = reinterpret_cast<const char*>(Ah + (size_t)arow * K + lhalf);
    const char* gAl = reinterpret_cast<const char*>(Al + (size_t)arow * K + lhalf);
    const char* gWh = reinterpret_cast<const char*>(Wh + (size_t)lrow * K + lhalf);
    const char* gWl = reinterpret_cast<const char*>(Wl + (size_t)lrow * K + lhalf);

    constexpr int NC = K / 64;

    // prefetch chunk 0 into stage 0
    {
        uint32_t s0 = sb + rowoff;
#pragma unroll
        for (int i = 0; i < 4; i++) {
            CP_ASYNC16(s0 + 0 * TILE_B + i * 16, gAh + i * 16, aSz);
            CP_ASYNC16(s0 + 1 * TILE_B + i * 16, gAl + i * 16, aSz);
            CP_ASYNC16(s0 + 2 * TILE_B + i * 16, gWh + i * 16, 16u);
            CP_ASYNC16(s0 + 3 * TILE_B + i * 16, gWl + i * 16, 16u);
        }
        CP_COMMIT();
    }

    if (tid < 128) {
        red0[tid] = 0.f;
        red1[tid] = 0.f;
        sbias[tid] = bias[tid];
    }

    float acc[2][8][4];
#pragma unroll
    for (int mt = 0; mt < 2; mt++)
#pragma unroll
        for (int nt = 0; nt < 8; nt++)
#pragma unroll
            for (int q = 0; q < 4; q++) acc[mt][nt][q] = 0.f;

#pragma unroll 1
    for (int c = 0; c < NC; c++) {
        if (c + 1 < NC) {
            uint32_t s1 = sb + ((c + 1) & 1) * STAGE_B + rowoff;
            int koff = (c + 1) * 128;  // 64 bf16 = 128 bytes
#pragma unroll
            for (int i = 0; i < 4; i++) {
                CP_ASYNC16(s1 + 0 * TILE_B + i * 16, gAh + koff + i * 16, aSz);
                CP_ASYNC16(s1 + 1 * TILE_B + i * 16, gAl + koff + i * 16, aSz);
                CP_ASYNC16(s1 + 2 * TILE_B + i * 16, gWh + koff + i * 16, 16u);
                CP_ASYNC16(s1 + 3 * TILE_B + i * 16, gWl + koff + i * 16, 16u);
            }
            CP_COMMIT();
            CP_WAIT1();
        } else {
            CP_WAIT0();
        }
        __syncthreads();

        const char* stg = dsm + (c & 1) * STAGE_B;
        const bf16* sAh = reinterpret_cast<const bf16*>(stg);
        const bf16* sAl = sAh + TILE_ELEMS;
        const bf16* sWh = sAl + TILE_ELEMS;
        const bf16* sWl = sWh + TILE_ELEMS;

#pragma unroll
        for (int kk = 0; kk < 4; kk++) {
            const int ac = kk * 16 + tig * 2;
            uint32_t aH[2][4], aL[2][4];
#pragma unroll
            for (int mt = 0; mt < 2; mt++) {
                int r = warp_m * 32 + mt * 16 + groupID;
                const bf16* pH = sAh + r * LDSTR + ac;
                const bf16* pL = sAl + r * LDSTR + ac;
                aH[mt][0] = *reinterpret_cast<const uint32_t*>(pH);
                aH[mt][1] = *reinterpret_cast<const uint32_t*>(pH + 8 * LDSTR);
                aH[mt][2] = *reinterpret_cast<const uint32_t*>(pH + 8);
                aH[mt][3] = *reinterpret_cast<const uint32_t*>(pH + 8 * LDSTR + 8);
                aL[mt][0] = *reinterpret_cast<const uint32_t*>(pL);
                aL[mt][1] = *reinterpret_cast<const uint32_t*>(pL + 8 * LDSTR);
                aL[mt][2] = *reinterpret_cast<const uint32_t*>(pL + 8);
                aL[mt][3] = *reinterpret_cast<const uint32_t*>(pL + 8 * LDSTR + 8);
            }
#pragma unroll
            for (int nt = 0; nt < 8; nt++) {
                int wr = warp_n * 64 + nt * 8 + groupID;
                const bf16* qH = sWh + wr * LDSTR + ac;
                const bf16* qL = sWl + wr * LDSTR + ac;
                uint32_t bH0 = *reinterpret_cast<const uint32_t*>(qH);
                uint32_t bH1 = *reinterpret_cast<const uint32_t*>(qH + 8);
                uint32_t bL0 = *reinterpret_cast<const uint32_t*>(qL);
                uint32_t bL1 = *reinterpret_cast<const uint32_t*>(qL + 8);
#pragma unroll
                for (int mt = 0; mt < 2; mt++) {
                    mma16816(acc[mt][nt], aH[mt], bH0, bH1);
                    mma16816(acc[mt][nt], aL[mt], bH0, bH1);
                    mma16816(acc[mt][nt], aH[mt], bL0, bL1);
                }
            }
        }
        __syncthreads();
    }

    // ---------------- epilogue: bias + relu + stats + store ----------------
#pragma unroll
    for (int mt = 0; mt < 2; mt++) {
        int r0 = rowBase + warp_m * 32 + mt * 16 + groupID;
        int r1 = r0 + 8;
#pragma unroll
        for (int nt = 0; nt < 8; nt++) {
            int j = warp_n * 64 + nt * 8 + tig * 2;
            float* a = acc[mt][nt];
            float b0v = sbias[j], b1v = sbias[j + 1];
            float v0 = (r0 < n) ? fmaxf(a[0] + b0v, 0.f) : 0.f;
            float v1 = (r0 < n) ? fmaxf(a[1] + b1v, 0.f) : 0.f;
            float v2 = (r1 < n) ? fmaxf(a[2] + b0v, 0.f) : 0.f;
            float v3 = (r1 < n) ? fmaxf(a[3] + b1v, 0.f) : 0.f;

            float s0 = v0 + v2, s1 = v1 + v3;
            float q0 = v0 * v0 + v2 * v2, q1 = v1 * v1 + v3 * v3;
#pragma unroll
            for (int off = 4; off < 32; off <<= 1) {
                s0 += __shfl_xor_sync(0xffffffffu, s0, off);
                s1 += __shfl_xor_sync(0xffffffffu, s1, off);
                q0 += __shfl_xor_sync(0xffffffffu, q0, off);
                q1 += __shfl_xor_sync(0xffffffffu, q1, off);
            }
            if (groupID == 0) {
                atomicAdd(red0 + j, s0);
                atomicAdd(red0 + j + 1, s1);
                atomicAdd(red1 + j, q0);
                atomicAdd(red1 + j + 1, q1);
            }

            if (LAST) {
                if (r0 < n)
                    *reinterpret_cast<float2*>(outF + (size_t)r0 * 128 + j) =
                        make_float2(v0, v1);
                if (r1 < n)
                    *reinterpret_cast<float2*>(outF + (size_t)r1 * 128 + j) =
                        make_float2(v2, v3);
            } else {
                if (r0 < n) {
                    bf16 h0 = __float2bfloat16_rn(v0);
                    bf16 h1 = __float2bfloat16_rn(v1);
                    __nv_bfloat162 hp; hp.x = h0; hp.y = h1;
                    *reinterpret_cast<uint32_t*>(Ch + (size_t)r0 * 128 + j) =
                        *reinterpret_cast<uint32_t*>(&hp);
                    *reinterpret_cast<uint32_t*>(Cl + (size_t)r0 * 128 + j) =
                        pack2bf(v0 - __bfloat162float(h0), v1 - __bfloat162float(h1));
                }
                if (r1 < n) {
                    bf16 h2 = __float2bfloat16_rn(v2);
                    bf16 h3 = __float2bfloat16_rn(v3);
                    __nv_bfloat162 hp; hp.x = h2; hp.y = h3;
                    *reinterpret_cast<uint32_t*>(Ch + (size_t)r1 * 128 + j) =
                        *reinterpret_cast<uint32_t*>(&hp);
                    *reinterpret_cast<uint32_t*>(Cl + (size_t)r1 * 128 + j) =
                        pack2bf(v2 - __bfloat162float(h2), v3 - __bfloat162float(h3));
                }
            }
        }
    }
    __syncthreads();
    if (tid < 128) {
        atomicAdd(&stats[tid], red0[tid]);
        atomicAdd(&stats[128 + tid], red1[tid]);
    }
}

// ============================ host launcher ==================================
extern "C" void kernel_launch(void* const* d_in, const int* in_sizes, int n_in,
                              void* d_out, int out_size) {
    const float* x = (const float*)d_in[0];
    const void* ei = d_in[1];
    const float* ea = (const float*)d_in[2];
    const float* u = (const float*)d_in[3];
    const void* batch = d_in[4];
    const float* W0 = (const float*)d_in[5];
    const float* b0 = (const float*)d_in[6];
    const float* W1 = (const float*)d_in[7];
    const float* b1 = (const float*)d_in[8];
    const float* W2 = (const float*)d_in[9];
    const float* b2 = (const float*)d_in[10];
    const float* g0 = (const float*)d_in[11];
    const float* be0 = (const float*)d_in[12];
    const float* g1 = (const float*)d_in[13];
    const float* be1 = (const float*)d_in[14];
    const float* g2 = (const float*)d_in[15];
    const float* be2 = (const float*)d_in[16];

    int n = in_sizes[0] / DIM;
    int nE = in_sizes[2] / DIM;
    int nG = in_sizes[3] / DIM;
    float* out = (float*)d_out;

    bf16 *combh, *combl, *h0h, *h0l, *h1h, *h1l;
    bf16 *w0h, *w0l, *wf1h, *wf1l, *wf2h, *wf2l;
    float *stats, *bf1, *bf2;
    cudaGetSymbolAddress((void**)&combh, g_combh);
    cudaGetSymbolAddress((void**)&combl, g_combl);
    cudaGetSymbolAddress((void**)&h0h, g_h0h);
    cudaGetSymbolAddress((void**)&h0l, g_h0l);
    cudaGetSymbolAddress((void**)&h1h, g_h1h);
    cudaGetSymbolAddress((void**)&h1l, g_h1l);
    cudaGetSymbolAddress((void**)&w0h, g_w0h);
    cudaGetSymbolAddress((void**)&w0l, g_w0l);
    cudaGetSymbolAddress((void**)&wf1h, g_wf1h);
    cudaGetSymbolAddress((void**)&wf1l, g_wf1l);
    cudaGetSymbolAddress((void**)&wf2h, g_wf2h);
    cudaGetSymbolAddress((void**)&wf2l, g_wf2l);
    cudaGetSymbolAddress((void**)&stats, g_stats);
    cudaGetSymbolAddress((void**)&bf1, g_bf1);
    cudaGetSymbolAddress((void**)&bf2, g_bf2);

    cudaFuncSetAttribute(gemm_mma<KBIG, false>,
                         cudaFuncAttributeMaxDynamicSharedMemorySize, GEMM_SMEM);
    cudaFuncSetAttribute(gemm_mma<DIM, false>,
                         cudaFuncAttributeMaxDynamicSharedMemorySize, GEMM_SMEM);
    cudaFuncSetAttribute(gemm_mma<DIM, true>,
                         cudaFuncAttributeMaxDynamicSharedMemorySize, GEMM_SMEM);

    int scanBlocks = (n + 1023) / 1024;

    detect_kernel<<<1, 256>>>((const int*)ei);
    zero_kernel<<<512, 256>>>();
    hist_kernel<<<(nE + 255) / 256, 256>>>(ei, nE, n);
    scan1_kernel<<<scanBlocks, 1024>>>(n);
    scan2_kernel<<<1, 32>>>(scanBlocks, n);
    scan3_kernel<<<scanBlocks, 1024>>>(n);
    fill_kernel<<<(nE + 255) / 256, 256>>>(ei, nE, n);
    gather_comb_kernel<<<(n * 32 + 255) / 256, 256>>>(ea, x, u, batch, n, nG);
    w0split_kernel<<<(DIM * KBIG + 255) / 256, 256>>>(W0);

    int gblocks = (n + 127) / 128;
    gemm_mma<KBIG, false><<<gblocks, 256, GEMM_SMEM>>>(
        combh, combl, w0h, w0l, b0, nullptr, h0h, h0l, stats, n);
    fold_kernel<<<1, 128>>>(stats, g0, be0, W1, b1, wf1h, wf1l, bf1, (float)n);
    gemm_mma<DIM, false><<<gblocks, 256, GEMM_SMEM>>>(
        h0h, h0l, wf1h, wf1l, bf1, nullptr, h1h, h1l, stats + 256, n);
    fold_kernel<<<1, 128>>>(stats + 256, g1, be1, W2, b2, wf2h, wf2l, bf2, (float)n);
    gemm_mma<DIM, true><<<gblocks, 256, GEMM_SMEM>>>(
        h1h, h1l, wf2h, wf2l, bf2, out, nullptr, nullptr, stats + 512, n);
    finalfold_kernel<<<1, 128>>>(stats + 512, g2, be2, (float)n);
    norm_kernel<<<1024, 256>>>(out, n);
}

// round 7
// speedup vs baseline: 1.0368x; 1.0021x over previous
#include <cuda_runtime.h>
#include <cuda_bf16.h>
#include <cstdint>

#define NN 50000
#define NE 600000
#define DIM 128
#define KBIG 384
#define BN_EPS 1e-5f

typedef __nv_bfloat16 bf16;

// ============================ scratch globals ================================
__device__ int g_deg[NN];
__device__ int g_off[NN + 1];
__device__ int g_cursor[NN];
__device__ int g_eid[NE];
__device__ int g_bsum[64];
__device__ bf16 g_combh[NN * KBIG];
__device__ bf16 g_combl[NN * KBIG];
__device__ bf16 g_h0h[NN * DIM];
__device__ bf16 g_h0l[NN * DIM];
__device__ bf16 g_h1h[NN * DIM];
__device__ bf16 g_h1l[NN * DIM];
__device__ bf16 g_w0h[DIM * KBIG];
__device__ bf16 g_w0l[DIM * KBIG];
__device__ bf16 g_wf1h[DIM * DIM];
__device__ bf16 g_wf1l[DIM * DIM];
__device__ bf16 g_wf2h[DIM * DIM];
__device__ bf16 g_wf2l[DIM * DIM];
__device__ float g_bf1[DIM];
__device__ float g_bf2[DIM];
__device__ float g_stats[3 * 2 * DIM];
__device__ float g_a2c2[2 * DIM];
__device__ int g_is64;

__device__ __forceinline__ uint32_t pack2bf(float a, float b) {
    __nv_bfloat162 t = __floats2bfloat162_rn(a, b);
    return *reinterpret_cast<uint32_t*>(&t);
}

__device__ __forceinline__ uint32_t smem_u32(const void* p) {
    uint32_t a;
    asm("{ .reg .u64 t; cvta.to.shared.u64 t, %1; cvt.u32.u64 %0, t; }"
        : "=r"(a) : "l"(p));
    return a;
}

#define CP_ASYNC16(dst, src, sz) \
    asm volatile("cp.async.ca.shared.global [%0], [%1], 16, %2;" \
                 :: "r"(dst), "l"(src), "r"(sz))
#define CP_COMMIT() asm volatile("cp.async.commit_group;" ::: "memory")
#define CP_WAIT0() asm volatile("cp.async.wait_group 0;" ::: "memory")
#define CP_WAIT1() asm volatile("cp.async.wait_group 1;" ::: "memory")

__device__ __forceinline__ int load_idx(const void* p, int i) {
    if (g_is64) return (int)((const long long*)p)[i];
    return ((const int*)p)[i];
}

// ============ prep: detect idx dtype + zero deg/stats + split W0 =============
__global__ void prep_kernel(const int* __restrict__ ei32,
                            const float* __restrict__ W0) {
    int gtid = blockIdx.x * blockDim.x + threadIdx.x;
    int stride = gridDim.x * blockDim.x;
    if (blockIdx.x == 0) {
        __shared__ int any;
        if (threadIdx.x == 0) any = 0;
        __syncthreads();
        for (int i = threadIdx.x; i < 1024; i += blockDim.x)
            if (ei32[2 * i + 1] != 0) atomicOr(&any, 1);
        __syncthreads();
        if (threadIdx.x == 0) g_is64 = (any == 0) ? 1 : 0;
    }
    for (int j = gtid; j < NN; j += stride) g_deg[j] = 0;
    for (int j = gtid; j < 3 * 2 * DIM; j += stride) g_stats[j] = 0.f;
    for (int i = gtid; i < DIM * KBIG; i += stride) {
        float w = W0[i];
        bf16 h = __float2bfloat16_rn(w);
        g_w0h[i] = h;
        g_w0l[i] = __float2bfloat16_rn(w - __bfloat162float(h));
    }
}

__global__ void hist_kernel(const void* __restrict__ ei, int nE, int n) {
    int e = blockIdx.x * blockDim.x + threadIdx.x;
    if (e >= nE) return;
    int src = load_idx(ei, e);
    if ((unsigned)src >= (unsigned)n) return;
    atomicAdd(&g_deg[src], 1);
}

// ---------- 2-phase parallel exclusive scan of g_deg -> g_off/g_cursor -------
__global__ void scan1_kernel(int n) {
    __shared__ int wsum[32];
    int tid = threadIdx.x;
    int lane = tid & 31;
    int wid = tid >> 5;
    int idx = blockIdx.x * 1024 + tid;
    int v = (idx < n) ? g_deg[idx] : 0;
    int x = v;
#pragma unroll
    for (int off = 1; off < 32; off <<= 1) {
        int t = __shfl_up_sync(0xffffffffu, x, off);
        if (lane >= off) x += t;
    }
    if (lane == 31) wsum[wid] = x;
    __syncthreads();
    if (wid == 0) {
        int w = wsum[lane];
        int y = w;
#pragma unroll
        for (int off = 1; off < 32; off <<= 1) {
            int t = __shfl_up_sync(0xffffffffu, y, off);
            if (lane >= off) y += t;
        }
        wsum[lane] = y - w;
    }
    __syncthreads();
    int excl = x - v + wsum[wid];
    if (idx < n) g_off[idx] = excl;
    if (tid == 1023) g_bsum[blockIdx.x] = excl + v;
}

__global__ void scan3_kernel(int n) {
    __shared__ int sprefix;
    int bid = blockIdx.x;
    if (threadIdx.x < 32) {
        int v = 0;
        if (threadIdx.x < bid) v = g_bsum[threadIdx.x];
        if (threadIdx.x + 32 < bid) v += g_bsum[threadIdx.x + 32];
#pragma unroll
        for (int off = 16; off; off >>= 1)
            v += __shfl_xor_sync(0xffffffffu, v, off);
        if (threadIdx.x == 0) sprefix = v;
    }
    __syncthreads();
    int idx = bid * 1024 + threadIdx.x;
    if (idx < n) {
        int o = g_off[idx] + sprefix;
        g_off[idx] = o;
        g_cursor[idx] = o;
    }
    if (bid == (int)gridDim.x - 1 && threadIdx.x == 0)
        g_off[n] = sprefix + g_bsum[bid];
}

__global__ void fill_kernel(const void* __restrict__ ei, int nE, int n) {
    int e = blockIdx.x * blockDim.x + threadIdx.x;
    if (e >= nE) return;
    int src = load_idx(ei, e);
    if ((unsigned)src >= (unsigned)n) return;
    int pos = atomicAdd(&g_cursor[src], 1);
    g_eid[pos] = e;
}

__device__ __forceinline__ void split4(float4 v, uint2& H, uint2& L) {
    bf16 h0 = __float2bfloat16_rn(v.x);
    bf16 h1 = __float2bfloat16_rn(v.y);
    bf16 h2 = __float2bfloat16_rn(v.z);
    bf16 h3 = __float2bfloat16_rn(v.w);
    float l0 = v.x - __bfloat162float(h0);
    float l1 = v.y - __bfloat162float(h1);
    float l2 = v.z - __bfloat162float(h2);
    float l3 = v.w - __bfloat162float(h3);
    __nv_bfloat162 p01; p01.x = h0; p01.y = h1;
    __nv_bfloat162 p23; p23.x = h2; p23.y = h3;
    H.x = *reinterpret_cast<uint32_t*>(&p01);
    H.y = *reinterpret_cast<uint32_t*>(&p23);
    L.x = pack2bf(l0, l1);
    L.y = pack2bf(l2, l3);
}

// one warp per node: gather-sum incident edges (MLP-4), build split-bf16 comb
__global__ void gather_comb_kernel(const float* __restrict__ ea,
                                   const float* __restrict__ x,
                                   const float* __restrict__ u,
                                   const void* __restrict__ batch,
                                   int n, int nG) {
    int t = blockIdx.x * blockDim.x + threadIdx.x;
    int node = t >> 5;
    int lane = t & 31;
    if (node >= n) return;
    int beg = g_off[node];
    int d = g_off[node + 1] - beg;

    const float4* ea4 = reinterpret_cast<const float4*>(ea);
    float4 a0 = make_float4(0.f, 0.f, 0.f, 0.f);
    float4 a1 = a0, a2 = a0, a3 = a0;
    for (int base = 0; base < d; base += 32) {
        int m = min(32, d - base);
        int eid = (lane < m) ? g_eid[beg + base + lane] : 0;
        int i = 0;
        for (; i + 4 <= m; i += 4) {
            int e0 = __shfl_sync(0xffffffffu, eid, i);
            int e1 = __shfl_sync(0xffffffffu, eid, i + 1);
            int e2 = __shfl_sync(0xffffffffu, eid, i + 2);
            int e3 = __shfl_sync(0xffffffffu, eid, i + 3);
            float4 v0 = ea4[(size_t)e0 * 32 + lane];
            float4 v1 = ea4[(size_t)e1 * 32 + lane];
            float4 v2 = ea4[(size_t)e2 * 32 + lane];
            float4 v3 = ea4[(size_t)e3 * 32 + lane];
            a0.x += v0.x; a0.y += v0.y; a0.z += v0.z; a0.w += v0.w;
            a1.x += v1.x; a1.y += v1.y; a1.z += v1.z; a1.w += v1.w;
            a2.x += v2.x; a2.y += v2.y; a2.z += v2.z; a2.w += v2.w;
            a3.x += v3.x; a3.y += v3.y; a3.z += v3.z; a3.w += v3.w;
        }
        for (; i < m; i++) {
            int e0 = __shfl_sync(0xffffffffu, eid, i);
            float4 v0 = ea4[(size_t)e0 * 32 + lane];
            a0.x += v0.x; a0.y += v0.y; a0.z += v0.z; a0.w += v0.w;
        }
    }
    float4 acc;
    acc.x = (a0.x + a1.x) + (a2.x + a3.x);
    acc.y = (a0.y + a1.y) + (a2.y + a3.y);
    acc.z = (a0.z + a1.z) + (a2.z + a3.z);
    acc.w = (a0.w + a1.w) + (a2.w + a3.w);
    float inv = 1.f / fmaxf((float)d, 1.f);
    acc.x *= inv; acc.y *= inv; acc.z *= inv; acc.w *= inv;

    int b = load_idx(batch, node);
    if ((unsigned)b >= (unsigned)nG) b = 0;
    float4 xv = reinterpret_cast<const float4*>(x)[(size_t)node * 32 + lane];
    float4 uv = reinterpret_cast<const float4*>(u)[(size_t)b * 32 + lane];

    uint2* ch = reinterpret_cast<uint2*>(g_combh);
    uint2* cl = reinterpret_cast<uint2*>(g_combl);
    size_t base = (size_t)node * 96;
    uint2 H, L;
    split4(xv, H, L);  ch[base + lane] = H;      cl[base + lane] = L;
    split4(acc, H, L); ch[base + 32 + lane] = H; cl[base + 32 + lane] = L;
    split4(uv, H, L);  ch[base + 64 + lane] = H; cl[base + 64 + lane] = L;
}

__global__ void fold_kernel(const float* __restrict__ stats,
                            const float* __restrict__ gamma,
                            const float* __restrict__ beta,
                            const float* __restrict__ Wn,
                            const float* __restrict__ bn,
                            bf16* __restrict__ Wh, bf16* __restrict__ Wl,
                            float* __restrict__ bf, float n) {
    __shared__ float a[128], c[128];
    int tid = threadIdx.x;
    float m = stats[tid] / n;
    float var = stats[128 + tid] / n - m * m;
    float rs = rsqrtf(var + BN_EPS);
    a[tid] = gamma[tid] * rs;
    c[tid] = beta[tid] - gamma[tid] * m * rs;
    __syncthreads();
    float accb = 0.f;
#pragma unroll 4
    for (int k = 0; k < 128; k++) {
        float w = Wn[tid * 128 + k];
        float wf = w * a[k];
        bf16 h = __float2bfloat16_rn(wf);
        Wh[tid * 128 + k] = h;
        Wl[tid * 128 + k] = __float2bfloat16_rn(wf - __bfloat162float(h));
        accb += c[k] * w;
    }
    bf[tid] = bn[tid] + accb;
}

__global__ void finalfold_kernel(const float* __restrict__ stats,
                                 const float* __restrict__ gamma,
                                 const float* __restrict__ beta, float n) {
    int tid = threadIdx.x;
    float m = stats[tid] / n;
    float var = stats[128 + tid] / n - m * m;
    float rs = rsqrtf(var + BN_EPS);
    g_a2c2[tid] = gamma[tid] * rs;
    g_a2c2[128 + tid] = beta[tid] - gamma[tid] * m * rs;
}

__global__ void norm_kernel(float* __restrict__ out, int n) {
    int i = blockIdx.x * blockDim.x + threadIdx.x;
    int stride = gridDim.x * blockDim.x;
    float4* o4 = reinterpret_cast<float4*>(out);
    const float4* a4 = reinterpret_cast<const float4*>(g_a2c2);
    const float4* c4 = reinterpret_cast<const float4*>(g_a2c2 + 128);
    for (int j = i; j < n * 32; j += stride) {
        int q = j & 31;
        float4 v = o4[j];
        float4 a = a4[q];
        float4 c = c4[q];
        v.x = v.x * a.x + c.x;
        v.y = v.y * a.y + c.y;
        v.z = v.z * a.z + c.z;
        v.w = v.w * a.w + c.w;
        o4[j] = v;
    }
}

// ====================== mma.sync bf16-split GEMM =============================
// K-chunk = 32, LDSTR = 40 -> 40KB/stage, 2 stages -> 2 CTAs/SM
__device__ __forceinline__ void mma16816(float* c, const uint32_t* a,
                                         uint32_t b0, uint32_t b1) {
    asm volatile(
        "mma.sync.aligned.m16n8k16.row.col.f32.bf16.bf16.f32 "
        "{%0,%1,%2,%3}, {%4,%5,%6,%7}, {%8,%9}, {%0,%1,%2,%3};"
        : "+f"(c[0]), "+f"(c[1]), "+f"(c[2]), "+f"(c[3])
        : "r"(a[0]), "r"(a[1]), "r"(a[2]), "r"(a[3]), "r"(b0), "r"(b1));
}

static constexpr int KCH = 32;
static constexpr int LDSTR = 40;                        // bf16 elems per row
static constexpr int TILE_ELEMS = 128 * LDSTR;          // 5120
static constexpr int TILE_B = TILE_ELEMS * 2;           // 10240 bytes
static constexpr int STAGE_B = 4 * TILE_B;              // 40960 bytes
static constexpr int GEMM_SMEM = 2 * STAGE_B + 3 * 128 * 4;

template <int K, bool LAST>
__global__ void __launch_bounds__(256, 2)
gemm_mma(const bf16* __restrict__ Ah, const bf16* __restrict__ Al,
         const bf16* __restrict__ Wh, const bf16* __restrict__ Wl,
         const float* __restrict__ bias, float* __restrict__ outF,
         bf16* __restrict__ Ch, bf16* __restrict__ Cl,
         float* __restrict__ stats, int n) {
    extern __shared__ __align__(16) char dsm[];
    float* red0 = reinterpret_cast<float*>(dsm + 2 * STAGE_B);
    float* red1 = red0 + 128;
    float* sbias = red1 + 128;

    const int tid = threadIdx.x;
    const int wid = tid >> 5;
    const int lane = tid & 31;
    const int warp_m = wid & 3;
    const int warp_n = wid >> 2;
    const int groupID = lane >> 2;
    const int tig = lane & 3;
    const int rowBase = blockIdx.x * 128;

    const int lrow = tid >> 1;
    const int lh16 = (tid & 1) * 16;  // 16-elem (32B) half within 32-elem chunk
    const bool rowOK = (rowBase + lrow) < n;
    const int arow = rowOK ? (rowBase + lrow) : (n - 1);
    const uint32_t aSz = rowOK ? 16u : 0u;

    const uint32_t sb = smem_u32(dsm);
    const uint32_t rowoff = (uint32_t)(lrow * LDSTR + lh16) * 2;

    const char* gAh = reinterpret_cast<const char*>(Ah + (size_t)arow * K + lh16);
    const char* gAl = reinterpret_cast<const char*>(Al + (size_t)arow * K + lh16);
    const char* gWh = reinterpret_cast<const char*>(Wh + (size_t)lrow * K + lh16);
    const char* gWl = reinterpret_cast<const char*>(Wl + (size_t)lrow * K + lh16);

    constexpr int NC = K / KCH;

    // prefetch chunk 0 into stage 0 (2 x 16B per tile per thread)
    {
        uint32_t s0 = sb + rowoff;
#pragma unroll
        for (int i = 0; i < 2; i++) {
            CP_ASYNC16(s0 + 0 * TILE_B + i * 16, gAh + i * 16, aSz);
            CP_ASYNC16(s0 + 1 * TILE_B + i * 16, gAl + i * 16, aSz);
            CP_ASYNC16(s0 + 2 * TILE_B + i * 16, gWh + i * 16, 16u);
            CP_ASYNC16(s0 + 3 * TILE_B + i * 16, gWl + i * 16, 16u);
        }
        CP_COMMIT();
    }

    if (tid < 128) {
        red0[tid] = 0.f;
        red1[tid] = 0.f;
        sbias[tid] = bias[tid];
    }

    float acc[2][8][4];
#pragma unroll
    for (int mt = 0; mt < 2; mt++)
#pragma unroll
        for (int nt = 0; nt < 8; nt++)
#pragma unroll
            for (int q = 0; q < 4; q++) acc[mt][nt][q] = 0.f;

#pragma unroll 1
    for (int c = 0; c < NC; c++) {
        if (c + 1 < NC) {
            uint32_t s1 = sb + ((c + 1) & 1) * STAGE_B + rowoff;
            int koff = (c + 1) * (KCH * 2);  // bytes
#pragma unroll
            for (int i = 0; i < 2; i++) {
                CP_ASYNC16(s1 + 0 * TILE_B + i * 16, gAh + koff + i * 16, aSz);
                CP_ASYNC16(s1 + 1 * TILE_B + i * 16, gAl + koff + i * 16, aSz);
                CP_ASYNC16(s1 + 2 * TILE_B + i * 16, gWh + koff + i * 16, 16u);
                CP_ASYNC16(s1 + 3 * TILE_B + i * 16, gWl + koff + i * 16, 16u);
            }
            CP_COMMIT();
            CP_WAIT1();
        } else {
            CP_WAIT0();
        }
        __syncthreads();

        const char* stg = dsm + (c & 1) * STAGE_B;
        const bf16* sAh = reinterpret_cast<const bf16*>(stg);
        const bf16* sAl = sAh + TILE_ELEMS;
        const bf16* sWh = sAl + TILE_ELEMS;
        const bf16* sWl = sWh + TILE_ELEMS;

#pragma unroll
        for (int kk = 0; kk < 2; kk++) {
            const int ac = kk * 16 + tig * 2;
            uint32_t aH[2][4], aL[2][4];
#pragma unroll
            for (int mt = 0; mt < 2; mt++) {
                int r = warp_m * 32 + mt * 16 + groupID;
                const bf16* pH = sAh + r * LDSTR + ac;
                const bf16* pL = sAl + r * LDSTR + ac;
                aH[mt][0] = *reinterpret_cast<const uint32_t*>(pH);
                aH[mt][1] = *reinterpret_cast<const uint32_t*>(pH + 8 * LDSTR);
                aH[mt][2] = *reinterpret_cast<const uint32_t*>(pH + 8);
                aH[mt][3] = *reinterpret_cast<const uint32_t*>(pH + 8 * LDSTR + 8);
                aL[mt][0] = *reinterpret_cast<const uint32_t*>(pL);
                aL[mt][1] = *reinterpret_cast<const uint32_t*>(pL + 8 * LDSTR);
                aL[mt][2] = *reinterpret_cast<const uint32_t*>(pL + 8);
                aL[mt][3] = *reinterpret_cast<const uint32_t*>(pL + 8 * LDSTR + 8);
            }
#pragma unroll
            for (int nt = 0; nt < 8; nt++) {
                int wr = warp_n * 64 + nt * 8 + groupID;
                const bf16* qH = sWh + wr * LDSTR + ac;
                const bf16* qL = sWl + wr * LDSTR + ac;
                uint32_t bH0 = *reinterpret_cast<const uint32_t*>(qH);
                uint32_t bH1 = *reinterpret_cast<const uint32_t*>(qH + 8);
                uint32_t bL0 = *reinterpret_cast<const uint32_t*>(qL);
                uint32_t bL1 = *reinterpret_cast<const uint32_t*>(qL + 8);
#pragma unroll
                for (int mt = 0; mt < 2; mt++) {
                    mma16816(acc[mt][nt], aH[mt], bH0, bH1);
                    mma16816(acc[mt][nt], aL[mt], bH0, bH1);
                    mma16816(acc[mt][nt], aH[mt], bL0, bL1);
                }
            }
        }
        __syncthreads();
    }

    // ---------------- epilogue: bias + relu + stats + store ----------------
#pragma unroll
    for (int mt = 0; mt < 2; mt++) {
        int r0 = rowBase + warp_m * 32 + mt * 16 + groupID;
        int r1 = r0 + 8;
#pragma unroll
        for (int nt = 0; nt < 8; nt++) {
            int j = warp_n * 64 + nt * 8 + tig * 2;
            float* a = acc[mt][nt];
            float b0v = sbias[j], b1v = sbias[j + 1];
            float v0 = (r0 < n) ? fmaxf(a[0] + b0v, 0.f) : 0.f;
            float v1 = (r0 < n) ? fmaxf(a[1] + b1v, 0.f) : 0.f;
            float v2 = (r1 < n) ? fmaxf(a[2] + b0v, 0.f) : 0.f;
            float v3 = (r1 < n) ? fmaxf(a[3] + b1v, 0.f) : 0.f;

            float s0 = v0 + v2, s1 = v1 + v3;
            float q0 = v0 * v0 + v2 * v2, q1 = v1 * v1 + v3 * v3;
#pragma unroll
            for (int off = 4; off < 32; off <<= 1) {
                s0 += __shfl_xor_sync(0xffffffffu, s0, off);
                s1 += __shfl_xor_sync(0xffffffffu, s1, off);
                q0 += __shfl_xor_sync(0xffffffffu, q0, off);
                q1 += __shfl_xor_sync(0xffffffffu, q1, off);
            }
            if (groupID == 0) {
                atomicAdd(red0 + j, s0);
                atomicAdd(red0 + j + 1, s1);
                atomicAdd(red1 + j, q0);
                atomicAdd(red1 + j + 1, q1);
            }

            if (LAST) {
                if (r0 < n)
                    *reinterpret_cast<float2*>(outF + (size_t)r0 * 128 + j) =
                        make_float2(v0, v1);
                if (r1 < n)
                    *reinterpret_cast<float2*>(outF + (size_t)r1 * 128 + j) =
                        make_float2(v2, v3);
            } else {
                if (r0 < n) {
                    bf16 h0 = __float2bfloat16_rn(v0);
                    bf16 h1 = __float2bfloat16_rn(v1);
                    __nv_bfloat162 hp; hp.x = h0; hp.y = h1;
                    *reinterpret_cast<uint32_t*>(Ch + (size_t)r0 * 128 + j) =
                        *reinterpret_cast<uint32_t*>(&hp);
                    *reinterpret_cast<uint32_t*>(Cl + (size_t)r0 * 128 + j) =
                        pack2bf(v0 - __bfloat162float(h0), v1 - __bfloat162float(h1));
                }
                if (r1 < n) {
                    bf16 h2 = __float2bfloat16_rn(v2);
                    bf16 h3 = __float2bfloat16_rn(v3);
                    __nv_bfloat162 hp; hp.x = h2; hp.y = h3;
                    *reinterpret_cast<uint32_t*>(Ch + (size_t)r1 * 128 + j) =
                        *reinterpret_cast<uint32_t*>(&hp);
                    *reinterpret_cast<uint32_t*>(Cl + (size_t)r1 * 128 + j) =
                        pack2bf(v2 - __bfloat162float(h2), v3 - __bfloat162float(h3));
                }
            }
        }
    }
    __syncthreads();
    if (tid < 128) {
        atomicAdd(&stats[tid], red0[tid]);
        atomicAdd(&stats[128 + tid], red1[tid]);
    }
}

// ============================ host launcher ==================================
extern "C" void kernel_launch(void* const* d_in, const int* in_sizes, int n_in,
                              void* d_out, int out_size) {
    const float* x = (const float*)d_in[0];
    const void* ei = d_in[1];
    const float* ea = (const float*)d_in[2];
    const float* u = (const float*)d_in[3];
    const void* batch = d_in[4];
    const float* W0 = (const float*)d_in[5];
    const float* b0 = (const float*)d_in[6];
    const float* W1 = (const float*)d_in[7];
    const float* b1 = (const float*)d_in[8];
    const float* W2 = (const float*)d_in[9];
    const float* b2 = (const float*)d_in[10];
    const float* g0 = (const float*)d_in[11];
    const float* be0 = (const float*)d_in[12];
    const float* g1 = (const float*)d_in[13];
    const float* be1 = (const float*)d_in[14];
    const float* g2 = (const float*)d_in[15];
    const float* be2 = (const float*)d_in[16];

    int n = in_sizes[0] / DIM;
    int nE = in_sizes[2] / DIM;
    int nG = in_sizes[3] / DIM;
    float* out = (float*)d_out;

    bf16 *combh, *combl, *h0h, *h0l, *h1h, *h1l;
    bf16 *w0h, *w0l, *wf1h, *wf1l, *wf2h, *wf2l;
    float *stats, *bf1, *bf2;
    cudaGetSymbolAddress((void**)&combh, g_combh);
    cudaGetSymbolAddress((void**)&combl, g_combl);
    cudaGetSymbolAddress((void**)&h0h, g_h0h);
    cudaGetSymbolAddress((void**)&h0l, g_h0l);
    cudaGetSymbolAddress((void**)&h1h, g_h1h);
    cudaGetSymbolAddress((void**)&h1l, g_h1l);
    cudaGetSymbolAddress((void**)&w0h, g_w0h);
    cudaGetSymbolAddress((void**)&w0l, g_w0l);
    cudaGetSymbolAddress((void**)&wf1h, g_wf1h);
    cudaGetSymbolAddress((void**)&wf1l, g_wf1l);
    cudaGetSymbolAddress((void**)&wf2h, g_wf2h);
    cudaGetSymbolAddress((void**)&wf2l, g_wf2l);
    cudaGetSymbolAddress((void**)&stats, g_stats);
    cudaGetSymbolAddress((void**)&bf1, g_bf1);
    cudaGetSymbolAddress((void**)&bf2, g_bf2);

    cudaFuncSetAttribute(gemm_mma<KBIG, false>,
                         cudaFuncAttributeMaxDynamicSharedMemorySize, GEMM_SMEM);
    cudaFuncSetAttribute(gemm_mma<DIM, false>,
                         cudaFuncAttributeMaxDynamicSharedMemorySize, GEMM_SMEM);
    cudaFuncSetAttribute(gemm_mma<DIM, true>,
                         cudaFuncAttributeMaxDynamicSharedMemorySize, GEMM_SMEM);

    int scanBlocks = (n + 1023) / 1024;

    prep_kernel<<<256, 256>>>((const int*)ei, W0);
    hist_kernel<<<(nE + 255) / 256, 256>>>(ei, nE, n);
    scan1_kernel<<<scanBlocks, 1024>>>(n);
    scan3_kernel<<<scanBlocks, 1024>>>(n);
    fill_kernel<<<(nE + 255) / 256, 256>>>(ei, nE, n);
    gather_comb_kernel<<<(n * 32 + 255) / 256, 256>>>(ea, x, u, batch, n, nG);

    int gblocks = (n + 127) / 128;
    gemm_mma<KBIG, false><<<gblocks, 256, GEMM_SMEM>>>(
        combh, combl, w0h, w0l, b0, nullptr, h0h, h0l, stats, n);
    fold_kernel<<<1, 128>>>(stats, g0, be0, W1, b1, wf1h, wf1l, bf1, (float)n);
    gemm_mma<DIM, false><<<gblocks, 256, GEMM_SMEM>>>(
        h0h, h0l, wf1h, wf1l, bf1, nullptr, h1h, h1l, stats + 256, n);
    fold_kernel<<<1, 128>>>(stats + 256, g1, be1, W2, b2, wf2h, wf2l, bf2, (float)n);
    gemm_mma<DIM, true><<<gblocks, 256, GEMM_SMEM>>>(
        h1h, h1l, wf2h, wf2l, bf2, out, nullptr, nullptr, stats + 512, n);
    finalfold_kernel<<<1, 128>>>(stats + 512, g2, be2, (float)n);
    norm_kernel<<<1024, 256>>>(out, n);
}

// round 8
// speedup vs baseline: 1.0597x; 1.0221x over previous
#include <cuda_runtime.h>
#include <cuda_bf16.h>
#include <cstdint>

#define NN 50000
#define NE 600000
#define DIM 128
#define KC0 256
#define BN_EPS 1e-5f

typedef __nv_bfloat16 bf16;

// ============================ scratch globals ================================
__device__ int g_deg[NN];
__device__ int g_off[NN + 1];
__device__ int g_cursor[NN];
__device__ int g_eid[NE];
__device__ int g_aggval[64];
__device__ int g_aggflag[64];
__device__ int g_done;
__device__ bf16 g_combh[NN * KC0];
__device__ bf16 g_combl[NN * KC0];
__device__ bf16 g_h0h[NN * DIM];
__device__ bf16 g_h0l[NN * DIM];
__device__ bf16 g_h1h[NN * DIM];
__device__ bf16 g_h1l[NN * DIM];
__device__ bf16 g_w0h[DIM * KC0];
__device__ bf16 g_w0l[DIM * KC0];
__device__ bf16 g_wf1h[DIM * DIM];
__device__ bf16 g_wf1l[DIM * DIM];
__device__ bf16 g_wf2h[DIM * DIM];
__device__ bf16 g_wf2l[DIM * DIM];
__device__ float g_ubias[DIM * DIM];        // per-graph folded u-term + b0
__device__ float g_bf1[DIM];
__device__ float g_bf2[DIM];
__device__ float g_stats[3 * 2 * DIM];
__device__ float g_a2c2[2 * DIM];
__device__ int g_is64;

__device__ __forceinline__ uint32_t pack2bf(float a, float b) {
    __nv_bfloat162 t = __floats2bfloat162_rn(a, b);
    return *reinterpret_cast<uint32_t*>(&t);
}

__device__ __forceinline__ uint32_t smem_u32(const void* p) {
    uint32_t a;
    asm("{ .reg .u64 t; cvta.to.shared.u64 t, %1; cvt.u32.u64 %0, t; }"
        : "=r"(a) : "l"(p));
    return a;
}

#define CP_ASYNC16(dst, src, sz) \
    asm volatile("cp.async.ca.shared.global [%0], [%1], 16, %2;" \
                 :: "r"(dst), "l"(src), "r"(sz))
#define CP_COMMIT() asm volatile("cp.async.commit_group;" ::: "memory")
#define CP_WAIT0() asm volatile("cp.async.wait_group 0;" ::: "memory")
#define CP_WAIT1() asm volatile("cp.async.wait_group 1;" ::: "memory")

__device__ __forceinline__ int load_idx(const void* p, int i) {
    if (g_is64) return (int)((const long long*)p)[i];
    return ((const int*)p)[i];
}

// ====== prep: detect idx dtype + zero scratch + split W0 (x|v_e cols) =======
__global__ void prep_kernel(const int* __restrict__ ei32,
                            const float* __restrict__ W0) {
    int gtid = blockIdx.x * blockDim.x + threadIdx.x;
    int stride = gridDim.x * blockDim.x;
    if (blockIdx.x == 0) {
        __shared__ int any;
        if (threadIdx.x == 0) any = 0;
        __syncthreads();
        for (int i = threadIdx.x; i < 1024; i += blockDim.x)
            if (ei32[2 * i + 1] != 0) atomicOr(&any, 1);
        __syncthreads();
        if (threadIdx.x == 0) g_is64 = (any == 0) ? 1 : 0;
    }
    for (int j = gtid; j < NN; j += stride) g_deg[j] = 0;
    for (int j = gtid; j < 3 * 2 * DIM; j += stride) g_stats[j] = 0.f;
    for (int j = gtid; j < 64; j += stride) g_aggflag[j] = 0;
    if (gtid == 0) g_done = 0;
    // split first 256 cols of each W0 row into bf16 hi/lo
    for (int i = gtid; i < DIM * KC0; i += stride) {
        int row = i >> 8;
        int col = i & 255;
        float w = W0[row * 384 + col];
        bf16 h = __float2bfloat16_rn(w);
        g_w0h[i] = h;
        g_w0l[i] = __float2bfloat16_rn(w - __bfloat162float(h));
    }
}

__global__ void hist_kernel(const void* __restrict__ ei, int nE, int n) {
    int e = blockIdx.x * blockDim.x + threadIdx.x;
    if (e >= nE) return;
    int src = load_idx(ei, e);
    if ((unsigned)src >= (unsigned)n) return;
    atomicAdd(&g_deg[src], 1);
}

// ====== single-pass scan (decoupled lookback) + CSR fill in one kernel ======
__global__ void __launch_bounds__(1024)
scanfill_kernel(const void* __restrict__ ei, int nE, int n, int nb) {
    int tid = threadIdx.x;
    int bid = blockIdx.x;

    if (bid < nb) {
        __shared__ int wsum[32];
        __shared__ int bprefix;
        int lane = tid & 31;
        int wid = tid >> 5;
        int idx = bid * 1024 + tid;
        int v = (idx < n) ? g_deg[idx] : 0;
        int x = v;
#pragma unroll
        for (int off = 1; off < 32; off <<= 1) {
            int t = __shfl_up_sync(0xffffffffu, x, off);
            if (lane >= off) x += t;
        }
        if (lane == 31) wsum[wid] = x;
        __syncthreads();
        if (wid == 0) {
            int w = wsum[lane];
            int y = w;
#pragma unroll
            for (int off = 1; off < 32; off <<= 1) {
                int t = __shfl_up_sync(0xffffffffu, y, off);
                if (lane >= off) y += t;
            }
            wsum[lane] = y - w;
        }
        __syncthreads();
        int excl = x - v + wsum[wid];
        // publish block aggregate
        if (tid == 1023) {
            g_aggval[bid] = excl + v;
            __threadfence();
            atomicExch(&g_aggflag[bid], 1);
        }
        // lookback (warp 0)
        if (wid == 0) {
            int acc = 0;
            for (int j = lane; j < bid; j += 32) {
                while (atomicAdd(&g_aggflag[j], 0) == 0) {}
                acc += atomicAdd(&g_aggval[j], 0);
            }
#pragma unroll
            for (int off = 16; off; off >>= 1)
                acc += __shfl_xor_sync(0xffffffffu, acc, off);
            if (lane == 0) bprefix = acc;
        }
        __syncthreads();
        int o = excl + bprefix;
        if (idx < n) {
            g_off[idx] = o;
            g_cursor[idx] = o;
        }
        if (bid == nb - 1 && tid == 1023) g_off[n] = o + v;
        __threadfence();
        __syncthreads();
        if (tid == 0) atomicAdd(&g_done, 1);
    }

    // fill phase: wait until all scan blocks published their cursors
    if (tid == 0) {
        while (atomicAdd(&g_done, 0) < nb) {}
    }
    __syncthreads();
    int stride = gridDim.x * blockDim.x;
    for (int e = bid * blockDim.x + tid; e < nE; e += stride) {
        int src = load_idx(ei, e);
        if ((unsigned)src >= (unsigned)n) continue;
        int pos = atomicAdd(&g_cursor[src], 1);
        g_eid[pos] = e;
    }
}

__device__ __forceinline__ void split4(float4 v, uint2& H, uint2& L) {
    bf16 h0 = __float2bfloat16_rn(v.x);
    bf16 h1 = __float2bfloat16_rn(v.y);
    bf16 h2 = __float2bfloat16_rn(v.z);
    bf16 h3 = __float2bfloat16_rn(v.w);
    float l0 = v.x - __bfloat162float(h0);
    float l1 = v.y - __bfloat162float(h1);
    float l2 = v.z - __bfloat162float(h2);
    float l3 = v.w - __bfloat162float(h3);
    __nv_bfloat162 p01; p01.x = h0; p01.y = h1;
    __nv_bfloat162 p23; p23.x = h2; p23.y = h3;
    H.x = *reinterpret_cast<uint32_t*>(&p01);
    H.y = *reinterpret_cast<uint32_t*>(&p23);
    L.x = pack2bf(l0, l1);
    L.y = pack2bf(l2, l3);
}

// one warp per node: gather-sum incident edges (MLP-4), comb = [x | v_e]
__global__ void gather_comb_kernel(const float* __restrict__ ea,
                                   const float* __restrict__ x, int n) {
    int t = blockIdx.x * blockDim.x + threadIdx.x;
    int node = t >> 5;
    int lane = t & 31;
    if (node >= n) return;
    int beg = g_off[node];
    int d = g_off[node + 1] - beg;

    const float4* ea4 = reinterpret_cast<const float4*>(ea);
    float4 a0 = make_float4(0.f, 0.f, 0.f, 0.f);
    float4 a1 = a0, a2 = a0, a3 = a0;
    for (int base = 0; base < d; base += 32) {
        int m = min(32, d - base);
        int eid = (lane < m) ? g_eid[beg + base + lane] : 0;
        int i = 0;
        for (; i + 4 <= m; i += 4) {
            int e0 = __shfl_sync(0xffffffffu, eid, i);
            int e1 = __shfl_sync(0xffffffffu, eid, i + 1);
            int e2 = __shfl_sync(0xffffffffu, eid, i + 2);
            int e3 = __shfl_sync(0xffffffffu, eid, i + 3);
            float4 v0 = ea4[(size_t)e0 * 32 + lane];
            float4 v1 = ea4[(size_t)e1 * 32 + lane];
            float4 v2 = ea4[(size_t)e2 * 32 + lane];
            float4 v3 = ea4[(size_t)e3 * 32 + lane];
            a0.x += v0.x; a0.y += v0.y; a0.z += v0.z; a0.w += v0.w;
            a1.x += v1.x; a1.y += v1.y; a1.z += v1.z; a1.w += v1.w;
            a2.x += v2.x; a2.y += v2.y; a2.z += v2.z; a2.w += v2.w;
            a3.x += v3.x; a3.y += v3.y; a3.z += v3.z; a3.w += v3.w;
        }
        for (; i < m; i++) {
            int e0 = __shfl_sync(0xffffffffu, eid, i);
            float4 v0 = ea4[(size_t)e0 * 32 + lane];
            a0.x += v0.x; a0.y += v0.y; a0.z += v0.z; a0.w += v0.w;
        }
    }
    float4 acc;
    acc.x = (a0.x + a1.x) + (a2.x + a3.x);
    acc.y = (a0.y + a1.y) + (a2.y + a3.y);
    acc.z = (a0.z + a1.z) + (a2.z + a3.z);
    acc.w = (a0.w + a1.w) + (a2.w + a3.w);
    float inv = 1.f / fmaxf((float)d, 1.f);
    acc.x *= inv; acc.y *= inv; acc.z *= inv; acc.w *= inv;

    float4 xv = reinterpret_cast<const float4*>(x)[(size_t)node * 32 + lane];

    uint2* ch = reinterpret_cast<uint2*>(g_combh);
    uint2* cl = reinterpret_cast<uint2*>(g_combl);
    size_t base = (size_t)node * 64;
    uint2 H, L;
    split4(xv, H, L);  ch[base + lane] = H;      cl[base + lane] = L;
    split4(acc, H, L); ch[base + 32 + lane] = H; cl[base + 32 + lane] = L;
}

// per-graph: ubias[g][j] = b0[j] + sum_k u[g,k] * W0[j, 256+k]
__global__ void ugemm_kernel(const float* __restrict__ u,
                             const float* __restrict__ W0,
                             const float* __restrict__ b0) {
    int g = blockIdx.x;
    int j = threadIdx.x;
    __shared__ float su[128];
    su[j] = u[g * 128 + j];
    __syncthreads();
    const float* w = W0 + (size_t)j * 384 + 256;
    float acc = b0[j];
#pragma unroll 4
    for (int k = 0; k < 128; k++) acc += su[k] * w[k];
    g_ubias[g * 128 + j] = acc;
}

__global__ void fold_kernel(const float* __restrict__ stats,
                            const float* __restrict__ gamma,
                            const float* __restrict__ beta,
                            const float* __restrict__ Wn,
                            const float* __restrict__ bn,
                            bf16* __restrict__ Wh, bf16* __restrict__ Wl,
                            float* __restrict__ bf, float n) {
    __shared__ float a[128], c[128];
    int tid = threadIdx.x;
    float m = stats[tid] / n;
    float var = stats[128 + tid] / n - m * m;
    float rs = rsqrtf(var + BN_EPS);
    a[tid] = gamma[tid] * rs;
    c[tid] = beta[tid] - gamma[tid] * m * rs;
    __syncthreads();
    float accb = 0.f;
#pragma unroll 4
    for (int k = 0; k < 128; k++) {
        float w = Wn[tid * 128 + k];
        float wf = w * a[k];
        bf16 h = __float2bfloat16_rn(wf);
        Wh[tid * 128 + k] = h;
        Wl[tid * 128 + k] = __float2bfloat16_rn(wf - __bfloat162float(h));
        accb += c[k] * w;
    }
    bf[tid] = bn[tid] + accb;
}

__global__ void finalfold_kernel(const float* __restrict__ stats,
                                 const float* __restrict__ gamma,
                                 const float* __restrict__ beta, float n) {
    int tid = threadIdx.x;
    float m = stats[tid] / n;
    float var = stats[128 + tid] / n - m * m;
    float rs = rsqrtf(var + BN_EPS);
    g_a2c2[tid] = gamma[tid] * rs;
    g_a2c2[128 + tid] = beta[tid] - gamma[tid] * m * rs;
}

__global__ void norm_kernel(float* __restrict__ out, int n) {
    int i = blockIdx.x * blockDim.x + threadIdx.x;
    int stride = gridDim.x * blockDim.x;
    float4* o4 = reinterpret_cast<float4*>(out);
    const float4* a4 = reinterpret_cast<const float4*>(g_a2c2);
    const float4* c4 = reinterpret_cast<const float4*>(g_a2c2 + 128);
    for (int j = i; j < n * 32; j += stride) {
        int q = j & 31;
        float4 v = o4[j];
        float4 a = a4[q];
        float4 c = c4[q];
        v.x = v.x * a.x + c.x;
        v.y = v.y * a.y + c.y;
        v.z = v.z * a.z + c.z;
        v.w = v.w * a.w + c.w;
        o4[j] = v;
    }
}

// ====================== mma.sync bf16-split GEMM =============================
__device__ __forceinline__ void mma16816(float* c, const uint32_t* a,
                                         uint32_t b0, uint32_t b1) {
    asm volatile(
        "mma.sync.aligned.m16n8k16.row.col.f32.bf16.bf16.f32 "
        "{%0,%1,%2,%3}, {%4,%5,%6,%7}, {%8,%9}, {%0,%1,%2,%3};"
        : "+f"(c[0]), "+f"(c[1]), "+f"(c[2]), "+f"(c[3])
        : "r"(a[0]), "r"(a[1]), "r"(a[2]), "r"(a[3]), "r"(b0), "r"(b1));
}

static constexpr int KCH = 32;
static constexpr int LDSTR = 40;
static constexpr int TILE_ELEMS = 128 * LDSTR;
static constexpr int TILE_B = TILE_ELEMS * 2;
static constexpr int STAGE_B = 4 * TILE_B;
static constexpr int GEMM_SMEM = 2 * STAGE_B + 3 * 128 * 4;

template <int K, bool LAST, bool UBIAS>
__global__ void __launch_bounds__(256, 2)
gemm_mma(const bf16* __restrict__ Ah, const bf16* __restrict__ Al,
         const bf16* __restrict__ Wh, const bf16* __restrict__ Wl,
         const float* __restrict__ bias, const float* __restrict__ ubias,
         const void* __restrict__ batch, float* __restrict__ outF,
         bf16* __restrict__ Ch, bf16* __restrict__ Cl,
         float* __restrict__ stats, int n) {
    extern __shared__ __align__(16) char dsm[];
    float* red0 = reinterpret_cast<float*>(dsm + 2 * STAGE_B);
    float* red1 = red0 + 128;
    float* sbias = red1 + 128;

    const int tid = threadIdx.x;
    const int wid = tid >> 5;
    const int lane = tid & 31;
    const int warp_m = wid & 3;
    const int warp_n = wid >> 2;
    const int groupID = lane >> 2;
    const int tig = lane & 3;
    const int rowBase = blockIdx.x * 128;

    const int lrow = tid >> 1;
    const int lh16 = (tid & 1) * 16;
    const bool rowOK = (rowBase + lrow) < n;
    const int arow = rowOK ? (rowBase + lrow) : (n - 1);
    const uint32_t aSz = rowOK ? 16u : 0u;

    const uint32_t sb = smem_u32(dsm);
    const uint32_t rowoff = (uint32_t)(lrow * LDSTR + lh16) * 2;

    const char* gAh = reinterpret_cast<const char*>(Ah + (size_t)arow * K + lh16);
    const char* gAl = reinterpret_cast<const char*>(Al + (size_t)arow * K + lh16);
    const char* gWh = reinterpret_cast<const char*>(Wh + (size_t)lrow * K + lh16);
    const char* gWl = reinterpret_cast<const char*>(Wl + (size_t)lrow * K + lh16);

    constexpr int NC = K / KCH;

    {
        uint32_t s0 = sb + rowoff;
#pragma unroll
        for (int i = 0; i < 2; i++) {
            CP_ASYNC16(s0 + 0 * TILE_B + i * 16, gAh + i * 16, aSz);
            CP_ASYNC16(s0 + 1 * TILE_B + i * 16, gAl + i * 16, aSz);
            CP_ASYNC16(s0 + 2 * TILE_B + i * 16, gWh + i * 16, 16u);
            CP_ASYNC16(s0 + 3 * TILE_B + i * 16, gWl + i * 16, 16u);
        }
        CP_COMMIT();
    }

    if (tid < 128) {
        red0[tid] = 0.f;
        red1[tid] = 0.f;
        if (!UBIAS) sbias[tid] = bias[tid];
    }

    float acc[2][8][4];
#pragma unroll
    for (int mt = 0; mt < 2; mt++)
#pragma unroll
        for (int nt = 0; nt < 8; nt++)
#pragma unroll
            for (int q = 0; q < 4; q++) acc[mt][nt][q] = 0.f;

#pragma unroll 1
    for (int c = 0; c < NC; c++) {
        if (c + 1 < NC) {
            uint32_t s1 = sb + ((c + 1) & 1) * STAGE_B + rowoff;
            int koff = (c + 1) * (KCH * 2);
#pragma unroll
            for (int i = 0; i < 2; i++) {
                CP_ASYNC16(s1 + 0 * TILE_B + i * 16, gAh + koff + i * 16, aSz);
                CP_ASYNC16(s1 + 1 * TILE_B + i * 16, gAl + koff + i * 16, aSz);
                CP_ASYNC16(s1 + 2 * TILE_B + i * 16, gWh + koff + i * 16, 16u);
                CP_ASYNC16(s1 + 3 * TILE_B + i * 16, gWl + koff + i * 16, 16u);
            }
            CP_COMMIT();
            CP_WAIT1();
        } else {
            CP_WAIT0();
        }
        __syncthreads();

        const char* stg = dsm + (c & 1) * STAGE_B;
        const bf16* sAh = reinterpret_cast<const bf16*>(stg);
        const bf16* sAl = sAh + TILE_ELEMS;
        const bf16* sWh = sAl + TILE_ELEMS;
        const bf16* sWl = sWh + TILE_ELEMS;

#pragma unroll
        for (int kk = 0; kk < 2; kk++) {
            const int ac = kk * 16 + tig * 2;
            uint32_t aH[2][4], aL[2][4];
#pragma unroll
            for (int mt = 0; mt < 2; mt++) {
                int r = warp_m * 32 + mt * 16 + groupID;
                const bf16* pH = sAh + r * LDSTR + ac;
                const bf16* pL = sAl + r * LDSTR + ac;
                aH[mt][0] = *reinterpret_cast<const uint32_t*>(pH);
                aH[mt][1] = *reinterpret_cast<const uint32_t*>(pH + 8 * LDSTR);
                aH[mt][2] = *reinterpret_cast<const uint32_t*>(pH + 8);
                aH[mt][3] = *reinterpret_cast<const uint32_t*>(pH + 8 * LDSTR + 8);
                aL[mt][0] = *reinterpret_cast<const uint32_t*>(pL);
                aL[mt][1] = *reinterpret_cast<const uint32_t*>(pL + 8 * LDSTR);
                aL[mt][2] = *reinterpret_cast<const uint32_t*>(pL + 8);
                aL[mt][3] = *reinterpret_cast<const uint32_t*>(pL + 8 * LDSTR + 8);
            }
#pragma unroll
            for (int nt = 0; nt < 8; nt++) {
                int wr = warp_n * 64 + nt * 8 + groupID;
                const bf16* qH = sWh + wr * LDSTR + ac;
                const bf16* qL = sWl + wr * LDSTR + ac;
                uint32_t bH0 = *reinterpret_cast<const uint32_t*>(qH);
                uint32_t bH1 = *reinterpret_cast<const uint32_t*>(qH + 8);
                uint32_t bL0 = *reinterpret_cast<const uint32_t*>(qL);
                uint32_t bL1 = *reinterpret_cast<const uint32_t*>(qL + 8);
#pragma unroll
                for (int mt = 0; mt < 2; mt++) {
                    mma16816(acc[mt][nt], aH[mt], bH0, bH1);
                    mma16816(acc[mt][nt], aL[mt], bH0, bH1);
                    mma16816(acc[mt][nt], aH[mt], bL0, bL1);
                }
            }
        }
        __syncthreads();
    }

    // ---------------- epilogue: bias + relu + stats + store ----------------
#pragma unroll
    for (int mt = 0; mt < 2; mt++) {
        int r0 = rowBase + warp_m * 32 + mt * 16 + groupID;
        int r1 = r0 + 8;
        const float* ub0 = sbias;
        const float* ub1 = sbias;
        if (UBIAS) {
            int b0i = (r0 < n) ? load_idx(batch, r0) : 0;
            int b1i = (r1 < n) ? load_idx(batch, r1) : 0;
            ub0 = ubias + (size_t)b0i * 128;
            ub1 = ubias + (size_t)b1i * 128;
        }
#pragma unroll
        for (int nt = 0; nt < 8; nt++) {
            int j = warp_n * 64 + nt * 8 + tig * 2;
            float* a = acc[mt][nt];
            float v0 = (r0 < n) ? fmaxf(a[0] + ub0[j], 0.f) : 0.f;
            float v1 = (r0 < n) ? fmaxf(a[1] + ub0[j + 1], 0.f) : 0.f;
            float v2 = (r1 < n) ? fmaxf(a[2] + ub1[j], 0.f) : 0.f;
            float v3 = (r1 < n) ? fmaxf(a[3] + ub1[j + 1], 0.f) : 0.f;

            float s0 = v0 + v2, s1 = v1 + v3;
            float q0 = v0 * v0 + v2 * v2, q1 = v1 * v1 + v3 * v3;
#pragma unroll
            for (int off = 4; off < 32; off <<= 1) {
                s0 += __shfl_xor_sync(0xffffffffu, s0, off);
                s1 += __shfl_xor_sync(0xffffffffu, s1, off);
                q0 += __shfl_xor_sync(0xffffffffu, q0, off);
                q1 += __shfl_xor_sync(0xffffffffu, q1, off);
            }
            if (groupID == 0) {
                atomicAdd(red0 + j, s0);
                atomicAdd(red0 + j + 1, s1);
                atomicAdd(red1 + j, q0);
                atomicAdd(red1 + j + 1, q1);
            }

            if (LAST) {
                if (r0 < n)
                    *reinterpret_cast<float2*>(outF + (size_t)r0 * 128 + j) =
                        make_float2(v0, v1);
                if (r1 < n)
                    *reinterpret_cast<float2*>(outF + (size_t)r1 * 128 + j) =
                        make_float2(v2, v3);
            } else {
                if (r0 < n) {
                    bf16 h0 = __float2bfloat16_rn(v0);
                    bf16 h1 = __float2bfloat16_rn(v1);
                    __nv_bfloat162 hp; hp.x = h0; hp.y = h1;
                    *reinterpret_cast<uint32_t*>(Ch + (size_t)r0 * 128 + j) =
                        *reinterpret_cast<uint32_t*>(&hp);
                    *reinterpret_cast<uint32_t*>(Cl + (size_t)r0 * 128 + j) =
                        pack2bf(v0 - __bfloat162float(h0), v1 - __bfloat162float(h1));
                }
                if (r1 < n) {
                    bf16 h2 = __float2bfloat16_rn(v2);
                    bf16 h3 = __float2bfloat16_rn(v3);
                    __nv_bfloat162 hp; hp.x = h2; hp.y = h3;
                    *reinterpret_cast<uint32_t*>(Ch + (size_t)r1 * 128 + j) =
                        *reinterpret_cast<uint32_t*>(&hp);
                    *reinterpret_cast<uint32_t*>(Cl + (size_t)r1 * 128 + j) =
                        pack2bf(v2 - __bfloat162float(h2), v3 - __bfloat162float(h3));
                }
            }
        }
    }
    __syncthreads();
    if (tid < 128) {
        atomicAdd(&stats[tid], red0[tid]);
        atomicAdd(&stats[128 + tid], red1[tid]);
    }
}

// ============================ host launcher ==================================
extern "C" void kernel_launch(void* const* d_in, const int* in_sizes, int n_in,
                              void* d_out, int out_size) {
    const float* x = (const float*)d_in[0];
    const void* ei = d_in[1];
    const float* ea = (const float*)d_in[2];
    const float* u = (const float*)d_in[3];
    const void* batch = d_in[4];
    const float* W0 = (const float*)d_in[5];
    const float* b0 = (const float*)d_in[6];
    const float* W1 = (const float*)d_in[7];
    const float* b1 = (const float*)d_in[8];
    const float* W2 = (const float*)d_in[9];
    const float* b2 = (const float*)d_in[10];
    const float* g0 = (const float*)d_in[11];
    const float* be0 = (const float*)d_in[12];
    const float* g1 = (const float*)d_in[13];
    const float* be1 = (const float*)d_in[14];
    const float* g2 = (const float*)d_in[15];
    const float* be2 = (const float*)d_in[16];

    int n = in_sizes[0] / DIM;
    int nE = in_sizes[2] / DIM;
    int nG = in_sizes[3] / DIM;
    float* out = (float*)d_out;

    bf16 *combh, *combl, *h0h, *h0l, *h1h, *h1l;
    bf16 *w0h, *w0l, *wf1h, *wf1l, *wf2h, *wf2l;
    float *stats, *bf1, *bf2, *ubias;
    cudaGetSymbolAddress((void**)&combh, g_combh);
    cudaGetSymbolAddress((void**)&combl, g_combl);
    cudaGetSymbolAddress((void**)&h0h, g_h0h);
    cudaGetSymbolAddress((void**)&h0l, g_h0l);
    cudaGetSymbolAddress((void**)&h1h, g_h1h);
    cudaGetSymbolAddress((void**)&h1l, g_h1l);
    cudaGetSymbolAddress((void**)&w0h, g_w0h);
    cudaGetSymbolAddress((void**)&w0l, g_w0l);
    cudaGetSymbolAddress((void**)&wf1h, g_wf1h);
    cudaGetSymbolAddress((void**)&wf1l, g_wf1l);
    cudaGetSymbolAddress((void**)&wf2h, g_wf2h);
    cudaGetSymbolAddress((void**)&wf2l, g_wf2l);
    cudaGetSymbolAddress((void**)&stats, g_stats);
    cudaGetSymbolAddress((void**)&bf1, g_bf1);
    cudaGetSymbolAddress((void**)&bf2, g_bf2);
    cudaGetSymbolAddress((void**)&ubias, g_ubias);

    cudaFuncSetAttribute(gemm_mma<KC0, false, true>,
                         cudaFuncAttributeMaxDynamicSharedMemorySize, GEMM_SMEM);
    cudaFuncSetAttribute(gemm_mma<DIM, false, false>,
                         cudaFuncAttributeMaxDynamicSharedMemorySize, GEMM_SMEM);
    cudaFuncSetAttribute(gemm_mma<DIM, true, false>,
                         cudaFuncAttributeMaxDynamicSharedMemorySize, GEMM_SMEM);

    int nb = (n + 1023) / 1024;  // scan blocks (49) — all resident, no deadlock

    prep_kernel<<<256, 256>>>((const int*)ei, W0);
    hist_kernel<<<(nE + 255) / 256, 256>>>(ei, nE, n);
    scanfill_kernel<<<256, 1024>>>(ei, nE, n, nb);
    gather_comb_kernel<<<(n * 32 + 255) / 256, 256>>>(ea, x, n);  // 4th: profiled
    ugemm_kernel<<<nG, 128>>>(u, W0, b0);

    int gblocks = (n + 127) / 128;
    gemm_mma<KC0, false, true><<<gblocks, 256, GEMM_SMEM>>>(
        combh, combl, w0h, w0l, nullptr, ubias, batch, nullptr, h0h, h0l, stats, n);
    fold_kernel<<<1, 128>>>(stats, g0, be0, W1, b1, wf1h, wf1l, bf1, (float)n);
    gemm_mma<DIM, false, false><<<gblocks, 256, GEMM_SMEM>>>(
        h0h, h0l, wf1h, wf1l, bf1, nullptr, nullptr, nullptr, h1h, h1l,
        stats + 256, n);
    fold_kernel<<<1, 128>>>(stats + 256, g1, be1, W2, b2, wf2h, wf2l, bf2, (float)n);
    gemm_mma<DIM, true, false><<<gblocks, 256, GEMM_SMEM>>>(
        h1h, h1l, wf2h, wf2l, bf2, nullptr, nullptr, out, nullptr, nullptr,
        stats + 512, n);
    finalfold_kernel<<<1, 128>>>(stats + 512, g2, be2, (float)n);
    norm_kernel<<<1024, 256>>>(out, n);
}

// round 9
// speedup vs baseline: 1.0849x; 1.0238x over previous
#include <cuda_runtime.h>
#include <cuda_bf16.h>
#include <cstdint>

#define NN 50000
#define NE 600000
#define DIM 128
#define KC0 256
#define BN_EPS 1e-5f

typedef __nv_bfloat16 bf16;

// ============================ scratch globals ================================
__device__ int g_deg[NN];
__device__ int g_off[NN + 1];
__device__ int g_cursor[NN];
__device__ int g_eid[NE];
__device__ int g_aggval[64];
__device__ int g_aggflag[64];
__device__ int g_done;
__device__ int g_done2;
__device__ bf16 g_combh[NN * KC0];
__device__ bf16 g_combl[NN * KC0];
__device__ bf16 g_h0h[NN * DIM];
__device__ bf16 g_h0l[NN * DIM];
__device__ bf16 g_h1h[NN * DIM];
__device__ bf16 g_h1l[NN * DIM];
__device__ bf16 g_w0h[DIM * KC0];
__device__ bf16 g_w0l[DIM * KC0];
__device__ bf16 g_wf1h[DIM * DIM];
__device__ bf16 g_wf1l[DIM * DIM];
__device__ bf16 g_wf2h[DIM * DIM];
__device__ bf16 g_wf2l[DIM * DIM];
__device__ float g_ubias[DIM * DIM];
__device__ float g_bf1[DIM];
__device__ float g_bf2[DIM];
__device__ float g_stats[3 * 2 * DIM];
__device__ float g_a2c2[2 * DIM];
__device__ int g_is64;

__device__ __forceinline__ uint32_t pack2bf(float a, float b) {
    __nv_bfloat162 t = __floats2bfloat162_rn(a, b);
    return *reinterpret_cast<uint32_t*>(&t);
}

__device__ __forceinline__ uint32_t smem_u32(const void* p) {
    uint32_t a;
    asm("{ .reg .u64 t; cvta.to.shared.u64 t, %1; cvt.u32.u64 %0, t; }"
        : "=r"(a) : "l"(p));
    return a;
}

#define CP_ASYNC16(dst, src, sz) \
    asm volatile("cp.async.ca.shared.global [%0], [%1], 16, %2;" \
                 :: "r"(dst), "l"(src), "r"(sz))
#define CP_COMMIT() asm volatile("cp.async.commit_group;" ::: "memory")
#define CP_WAIT0() asm volatile("cp.async.wait_group 0;" ::: "memory")
#define CP_WAIT1() asm volatile("cp.async.wait_group 1;" ::: "memory")

__device__ __forceinline__ int load_idx(const void* p, int i) {
    if (g_is64) return (int)((const long long*)p)[i];
    return ((const int*)p)[i];
}

// == prep: detect dtype + zero scratch + split W0 (x|v_e) + per-graph ubias ==
__global__ void prep_kernel(const int* __restrict__ ei32,
                            const float* __restrict__ W0,
                            const float* __restrict__ b0,
                            const float* __restrict__ u, int nG) {
    int gtid = blockIdx.x * blockDim.x + threadIdx.x;
    int stride = gridDim.x * blockDim.x;
    if (blockIdx.x == 0) {
        __shared__ int any;
        if (threadIdx.x == 0) any = 0;
        __syncthreads();
        for (int i = threadIdx.x; i < 1024; i += blockDim.x)
            if (ei32[2 * i + 1] != 0) atomicOr(&any, 1);
        __syncthreads();
        if (threadIdx.x == 0) g_is64 = (any == 0) ? 1 : 0;
    }
    for (int j = gtid; j < NN; j += stride) g_deg[j] = 0;
    for (int j = gtid; j < 3 * 2 * DIM; j += stride) g_stats[j] = 0.f;
    for (int j = gtid; j < 64; j += stride) g_aggflag[j] = 0;
    if (gtid == 0) { g_done = 0; g_done2 = 0; }
    for (int i = gtid; i < DIM * KC0; i += stride) {
        int row = i >> 8;
        int col = i & 255;
        float w = W0[row * 384 + col];
        bf16 h = __float2bfloat16_rn(w);
        g_w0h[i] = h;
        g_w0l[i] = __float2bfloat16_rn(w - __bfloat162float(h));
    }
    // blocks [128, 128+nG): ubias[g][j] = b0[j] + sum_k u[g,k]*W0[j,256+k]
    int g = (int)blockIdx.x - 128;
    if (g >= 0 && g < nG && threadIdx.x < 128) {
        __shared__ float su[128];
        int j = threadIdx.x;
        su[j] = u[g * 128 + j];
        __syncthreads();
        const float* w = W0 + (size_t)j * 384 + 256;
        float acc = b0[j];
#pragma unroll 4
        for (int k = 0; k < 128; k++) acc += su[k] * w[k];
        g_ubias[g * 128 + j] = acc;
    }
}

__global__ void hist_kernel(const void* __restrict__ ei, int nE, int n) {
    int e = blockIdx.x * blockDim.x + threadIdx.x;
    if (e >= nE) return;
    int src = load_idx(ei, e);
    if ((unsigned)src >= (unsigned)n) return;
    atomicAdd(&g_deg[src], 1);
}

__device__ __forceinline__ void split4(float4 v, uint2& H, uint2& L) {
    bf16 h0 = __float2bfloat16_rn(v.x);
    bf16 h1 = __float2bfloat16_rn(v.y);
    bf16 h2 = __float2bfloat16_rn(v.z);
    bf16 h3 = __float2bfloat16_rn(v.w);
    float l0 = v.x - __bfloat162float(h0);
    float l1 = v.y - __bfloat162float(h1);
    float l2 = v.z - __bfloat162float(h2);
    float l3 = v.w - __bfloat162float(h3);
    __nv_bfloat162 p01; p01.x = h0; p01.y = h1;
    __nv_bfloat162 p23; p23.x = h2; p23.y = h3;
    H.x = *reinterpret_cast<uint32_t*>(&p01);
    H.y = *reinterpret_cast<uint32_t*>(&p23);
    L.x = pack2bf(l0, l1);
    L.y = pack2bf(l2, l3);
}

// ====== persistent: scan (lookback) + CSR fill + gather/comb, one kernel =====
// grid = 148 blocks x 1024 thr, 1 block/SM -> all resident, spin-safe
__global__ void __launch_bounds__(1024, 1)
scanfill_gather_kernel(const void* __restrict__ ei,
                       const float* __restrict__ ea,
                       const float* __restrict__ x,
                       int nE, int n, int nb) {
    int tid = threadIdx.x;
    int bid = blockIdx.x;
    int lane = tid & 31;
    int wid = tid >> 5;

    // ---------------- phase 1: block scans + decoupled lookback -------------
    if (bid < nb) {
        __shared__ int wsum[32];
        __shared__ int bprefix;
        int idx = bid * 1024 + tid;
        int v = (idx < n) ? g_deg[idx] : 0;
        int xs = v;
#pragma unroll
        for (int off = 1; off < 32; off <<= 1) {
            int t = __shfl_up_sync(0xffffffffu, xs, off);
            if (lane >= off) xs += t;
        }
        if (lane == 31) wsum[wid] = xs;
        __syncthreads();
        if (wid == 0) {
            int w = wsum[lane];
            int y = w;
#pragma unroll
            for (int off = 1; off < 32; off <<= 1) {
                int t = __shfl_up_sync(0xffffffffu, y, off);
                if (lane >= off) y += t;
            }
            wsum[lane] = y - w;
        }
        __syncthreads();
        int excl = xs - v + wsum[wid];
        if (tid == 1023) {
            g_aggval[bid] = excl + v;
            __threadfence();
            atomicExch(&g_aggflag[bid], 1);
        }
        if (wid == 0) {
            int acc = 0;
            for (int j = lane; j < bid; j += 32) {
                while (atomicAdd(&g_aggflag[j], 0) == 0) {}
                acc += atomicAdd(&g_aggval[j], 0);
            }
#pragma unroll
            for (int off = 16; off; off >>= 1)
                acc += __shfl_xor_sync(0xffffffffu, acc, off);
            if (lane == 0) bprefix = acc;
        }
        __syncthreads();
        int o = excl + bprefix;
        if (idx < n) {
            g_off[idx] = o;
            g_cursor[idx] = o;
        }
        if (bid == nb - 1 && tid == 1023) g_off[n] = o + v;
        __threadfence();
        __syncthreads();
        if (tid == 0) atomicAdd(&g_done, 1);
    }

    // barrier: cursors ready
    if (tid == 0) while (atomicAdd(&g_done, 0) < nb) {}
    __syncthreads();

    // ---------------- phase 2: CSR fill -------------------------------------
    int stride = gridDim.x * blockDim.x;
    for (int e = bid * blockDim.x + tid; e < nE; e += stride) {
        int src = load_idx(ei, e);
        if ((unsigned)src >= (unsigned)n) continue;
        int pos = atomicAdd(&g_cursor[src], 1);
        g_eid[pos] = e;
    }
    __threadfence();
    __syncthreads();
    if (tid == 0) atomicAdd(&g_done2, 1);
    if (tid == 0) while (atomicAdd(&g_done2, 0) < (int)gridDim.x) {}
    __syncthreads();

    // ---------------- phase 3: gather + comb build (per-warp node loop) -----
    const float4* ea4 = reinterpret_cast<const float4*>(ea);
    uint2* ch = reinterpret_cast<uint2*>(g_combh);
    uint2* cl = reinterpret_cast<uint2*>(g_combl);
    int gw = (bid * 1024 + tid) >> 5;
    int nw = (gridDim.x * 1024) >> 5;
    for (int node = gw; node < n; node += nw) {
        int beg = g_off[node];
        int d = g_off[node + 1] - beg;

        float4 a0 = make_float4(0.f, 0.f, 0.f, 0.f);
        float4 a1 = a0, a2 = a0, a3 = a0;
        for (int base = 0; base < d; base += 32) {
            int m = min(32, d - base);
            int eid = (lane < m) ? g_eid[beg + base + lane] : 0;
            int i = 0;
            for (; i + 4 <= m; i += 4) {
                int e0 = __shfl_sync(0xffffffffu, eid, i);
                int e1 = __shfl_sync(0xffffffffu, eid, i + 1);
                int e2 = __shfl_sync(0xffffffffu, eid, i + 2);
                int e3 = __shfl_sync(0xffffffffu, eid, i + 3);
                float4 v0 = __ldcs(ea4 + (size_t)e0 * 32 + lane);
                float4 v1 = __ldcs(ea4 + (size_t)e1 * 32 + lane);
                float4 v2 = __ldcs(ea4 + (size_t)e2 * 32 + lane);
                float4 v3 = __ldcs(ea4 + (size_t)e3 * 32 + lane);
                a0.x += v0.x; a0.y += v0.y; a0.z += v0.z; a0.w += v0.w;
                a1.x += v1.x; a1.y += v1.y; a1.z += v1.z; a1.w += v1.w;
                a2.x += v2.x; a2.y += v2.y; a2.z += v2.z; a2.w += v2.w;
                a3.x += v3.x; a3.y += v3.y; a3.z += v3.z; a3.w += v3.w;
            }
            for (; i < m; i++) {
                int e0 = __shfl_sync(0xffffffffu, eid, i);
                float4 v0 = __ldcs(ea4 + (size_t)e0 * 32 + lane);
                a0.x += v0.x; a0.y += v0.y; a0.z += v0.z; a0.w += v0.w;
            }
        }
        float4 acc;
        acc.x = (a0.x + a1.x) + (a2.x + a3.x);
        acc.y = (a0.y + a1.y) + (a2.y + a3.y);
        acc.z = (a0.z + a1.z) + (a2.z + a3.z);
        acc.w = (a0.w + a1.w) + (a2.w + a3.w);
        float inv = 1.f / fmaxf((float)d, 1.f);
        acc.x *= inv; acc.y *= inv; acc.z *= inv; acc.w *= inv;

        float4 xv = reinterpret_cast<const float4*>(x)[(size_t)node * 32 + lane];

        size_t cb = (size_t)node * 64;
        uint2 H, L;
        split4(xv, H, L);  ch[cb + lane] = H;      cl[cb + lane] = L;
        split4(acc, H, L); ch[cb + 32 + lane] = H; cl[cb + 32 + lane] = L;
    }
}

__global__ void fold_kernel(const float* __restrict__ stats,
                            const float* __restrict__ gamma,
                            const float* __restrict__ beta,
                            const float* __restrict__ Wn,
                            const float* __restrict__ bn,
                            bf16* __restrict__ Wh, bf16* __restrict__ Wl,
                            float* __restrict__ bf, float n) {
    __shared__ float a[128], c[128];
    int tid = threadIdx.x;
    float m = stats[tid] / n;
    float var = stats[128 + tid] / n - m * m;
    float rs = rsqrtf(var + BN_EPS);
    a[tid] = gamma[tid] * rs;
    c[tid] = beta[tid] - gamma[tid] * m * rs;
    __syncthreads();
    float accb = 0.f;
#pragma unroll 4
    for (int k = 0; k < 128; k++) {
        float w = Wn[tid * 128 + k];
        float wf = w * a[k];
        bf16 h = __float2bfloat16_rn(wf);
        Wh[tid * 128 + k] = h;
        Wl[tid * 128 + k] = __float2bfloat16_rn(wf - __bfloat162float(h));
        accb += c[k] * w;
    }
    bf[tid] = bn[tid] + accb;
}

__global__ void finalfold_kernel(const float* __restrict__ stats,
                                 const float* __restrict__ gamma,
                                 const float* __restrict__ beta, float n) {
    int tid = threadIdx.x;
    float m = stats[tid] / n;
    float var = stats[128 + tid] / n - m * m;
    float rs = rsqrtf(var + BN_EPS);
    g_a2c2[tid] = gamma[tid] * rs;
    g_a2c2[128 + tid] = beta[tid] - gamma[tid] * m * rs;
}

__global__ void norm_kernel(float* __restrict__ out, int n) {
    int i = blockIdx.x * blockDim.x + threadIdx.x;
    int stride = gridDim.x * blockDim.x;
    float4* o4 = reinterpret_cast<float4*>(out);
    const float4* a4 = reinterpret_cast<const float4*>(g_a2c2);
    const float4* c4 = reinterpret_cast<const float4*>(g_a2c2 + 128);
    for (int j = i; j < n * 32; j += stride) {
        int q = j & 31;
        float4 v = o4[j];
        float4 a = a4[q];
        float4 c = c4[q];
        v.x = v.x * a.x + c.x;
        v.y = v.y * a.y + c.y;
        v.z = v.z * a.z + c.z;
        v.w = v.w * a.w + c.w;
        o4[j] = v;
    }
}

// ====================== mma.sync bf16-split GEMM =============================
__device__ __forceinline__ void mma16816(float* c, const uint32_t* a,
                                         uint32_t b0, uint32_t b1) {
    asm volatile(
        "mma.sync.aligned.m16n8k16.row.col.f32.bf16.bf16.f32 "
        "{%0,%1,%2,%3}, {%4,%5,%6,%7}, {%8,%9}, {%0,%1,%2,%3};"
        : "+f"(c[0]), "+f"(c[1]), "+f"(c[2]), "+f"(c[3])
        : "r"(a[0]), "r"(a[1]), "r"(a[2]), "r"(a[3]), "r"(b0), "r"(b1));
}

static constexpr int KCH = 32;
static constexpr int LDSTR = 40;
static constexpr int TILE_ELEMS = 128 * LDSTR;
static constexpr int TILE_B = TILE_ELEMS * 2;
static constexpr int STAGE_B = 4 * TILE_B;
static constexpr int GEMM_SMEM = 2 * STAGE_B + 3 * 128 * 4;

template <int K, bool LAST, bool UBIAS>
__global__ void __launch_bounds__(256, 2)
gemm_mma(const bf16* __restrict__ Ah, const bf16* __restrict__ Al,
         const bf16* __restrict__ Wh, const bf16* __restrict__ Wl,
         const float* __restrict__ bias, const float* __restrict__ ubias,
         const void* __restrict__ batch, float* __restrict__ outF,
         bf16* __restrict__ Ch, bf16* __restrict__ Cl,
         float* __restrict__ stats, int n) {
    extern __shared__ __align__(16) char dsm[];
    float* red0 = reinterpret_cast<float*>(dsm + 2 * STAGE_B);
    float* red1 = red0 + 128;
    float* sbias = red1 + 128;

    const int tid = threadIdx.x;
    const int wid = tid >> 5;
    const int lane = tid & 31;
    const int warp_m = wid & 3;
    const int warp_n = wid >> 2;
    const int groupID = lane >> 2;
    const int tig = lane & 3;
    const int rowBase = blockIdx.x * 128;

    const int lrow = tid >> 1;
    const int lh16 = (tid & 1) * 16;
    const bool rowOK = (rowBase + lrow) < n;
    const int arow = rowOK ? (rowBase + lrow) : (n - 1);
    const uint32_t aSz = rowOK ? 16u : 0u;

    const uint32_t sb = smem_u32(dsm);
    const uint32_t rowoff = (uint32_t)(lrow * LDSTR + lh16) * 2;

    const char* gAh = reinterpret_cast<const char*>(Ah + (size_t)arow * K + lh16);
    const char* gAl = reinterpret_cast<const char*>(Al + (size_t)arow * K + lh16);
    const char* gWh = reinterpret_cast<const char*>(Wh + (size_t)lrow * K + lh16);
    const char* gWl = reinterpret_cast<const char*>(Wl + (size_t)lrow * K + lh16);

    constexpr int NC = K / KCH;

    {
        uint32_t s0 = sb + rowoff;
#pragma unroll
        for (int i = 0; i < 2; i++) {
            CP_ASYNC16(s0 + 0 * TILE_B + i * 16, gAh + i * 16, aSz);
            CP_ASYNC16(s0 + 1 * TILE_B + i * 16, gAl + i * 16, aSz);
            CP_ASYNC16(s0 + 2 * TILE_B + i * 16, gWh + i * 16, 16u);
            CP_ASYNC16(s0 + 3 * TILE_B + i * 16, gWl + i * 16, 16u);
        }
        CP_COMMIT();
    }

    if (tid < 128) {
        red0[tid] = 0.f;
        red1[tid] = 0.f;
        if (!UBIAS) sbias[tid] = bias[tid];
    }

    float acc[2][8][4];
#pragma unroll
    for (int mt = 0; mt < 2; mt++)
#pragma unroll
        for (int nt = 0; nt < 8; nt++)
#pragma unroll
            for (int q = 0; q < 4; q++) acc[mt][nt][q] = 0.f;

#pragma unroll 1
    for (int c = 0; c < NC; c++) {
        if (c + 1 < NC) {
            uint32_t s1 = sb + ((c + 1) & 1) * STAGE_B + rowoff;
            int koff = (c + 1) * (KCH * 2);
#pragma unroll
            for (int i = 0; i < 2; i++) {
                CP_ASYNC16(s1 + 0 * TILE_B + i * 16, gAh + koff + i * 16, aSz);
                CP_ASYNC16(s1 + 1 * TILE_B + i * 16, gAl + koff + i * 16, aSz);
                CP_ASYNC16(s1 + 2 * TILE_B + i * 16, gWh + koff + i * 16, 16u);
                CP_ASYNC16(s1 + 3 * TILE_B + i * 16, gWl + koff + i * 16, 16u);
            }
            CP_COMMIT();
            CP_WAIT1();
        } else {
            CP_WAIT0();
        }
        __syncthreads();

        const char* stg = dsm + (c & 1) * STAGE_B;
        const bf16* sAh = reinterpret_cast<const bf16*>(stg);
        const bf16* sAl = sAh + TILE_ELEMS;
        const bf16* sWh = sAl + TILE_ELEMS;
        const bf16* sWl = sWh + TILE_ELEMS;

#pragma unroll
        for (int kk = 0; kk < 2; kk++) {
            const int ac = kk * 16 + tig * 2;
            uint32_t aH[2][4], aL[2][4];
#pragma unroll
            for (int mt = 0; mt < 2; mt++) {
                int r = warp_m * 32 + mt * 16 + groupID;
                const bf16* pH = sAh + r * LDSTR + ac;
                const bf16* pL = sAl + r * LDSTR + ac;
                aH[mt][0] = *reinterpret_cast<const uint32_t*>(pH);
                aH[mt][1] = *reinterpret_cast<const uint32_t*>(pH + 8 * LDSTR);
                aH[mt][2] = *reinterpret_cast<const uint32_t*>(pH + 8);
                aH[mt][3] = *reinterpret_cast<const uint32_t*>(pH + 8 * LDSTR + 8);
                aL[mt][0] = *reinterpret_cast<const uint32_t*>(pL);
                aL[mt][1] = *reinterpret_cast<const uint32_t*>(pL + 8 * LDSTR);
                aL[mt][2] = *reinterpret_cast<const uint32_t*>(pL + 8);
                aL[mt][3] = *reinterpret_cast<const uint32_t*>(pL + 8 * LDSTR + 8);
            }
#pragma unroll
            for (int nt = 0; nt < 8; nt++) {
                int wr = warp_n * 64 + nt * 8 + groupID;
                const bf16* qH = sWh + wr * LDSTR + ac;
                const bf16* qL = sWl + wr * LDSTR + ac;
                uint32_t bH0 = *reinterpret_cast<const uint32_t*>(qH);
                uint32_t bH1 = *reinterpret_cast<const uint32_t*>(qH + 8);
                uint32_t bL0 = *reinterpret_cast<const uint32_t*>(qL);
                uint32_t bL1 = *reinterpret_cast<const uint32_t*>(qL + 8);
#pragma unroll
                for (int mt = 0; mt < 2; mt++) {
                    mma16816(acc[mt][nt], aH[mt], bH0, bH1);
                    mma16816(acc[mt][nt], aL[mt], bH0, bH1);
                    mma16816(acc[mt][nt], aH[mt], bL0, bL1);
                }
            }
        }
        __syncthreads();
    }

    // ---------------- epilogue: bias + relu + stats + store ----------------
#pragma unroll
    for (int mt = 0; mt < 2; mt++) {
        int r0 = rowBase + warp_m * 32 + mt * 16 + groupID;
        int r1 = r0 + 8;
        const float* ub0 = sbias;
        const float* ub1 = sbias;
        if (UBIAS) {
            int b0i = (r0 < n) ? load_idx(batch, r0) : 0;
            int b1i = (r1 < n) ? load_idx(batch, r1) : 0;
            ub0 = ubias + (size_t)b0i * 128;
            ub1 = ubias + (size_t)b1i * 128;
        }
#pragma unroll
        for (int nt = 0; nt < 8; nt++) {
            int j = warp_n * 64 + nt * 8 + tig * 2;
            float* a = acc[mt][nt];
            float v0 = (r0 < n) ? fmaxf(a[0] + ub0[j], 0.f) : 0.f;
            float v1 = (r0 < n) ? fmaxf(a[1] + ub0[j + 1], 0.f) : 0.f;
            float v2 = (r1 < n) ? fmaxf(a[2] + ub1[j], 0.f) : 0.f;
            float v3 = (r1 < n) ? fmaxf(a[3] + ub1[j + 1], 0.f) : 0.f;

            float s0 = v0 + v2, s1 = v1 + v3;
            float q0 = v0 * v0 + v2 * v2, q1 = v1 * v1 + v3 * v3;
#pragma unroll
            for (int off = 4; off < 32; off <<= 1) {
                s0 += __shfl_xor_sync(0xffffffffu, s0, off);
                s1 += __shfl_xor_sync(0xffffffffu, s1, off);
                q0 += __shfl_xor_sync(0xffffffffu, q0, off);
                q1 += __shfl_xor_sync(0xffffffffu, q1, off);
            }
            if (groupID == 0) {
                atomicAdd(red0 + j, s0);
                atomicAdd(red0 + j + 1, s1);
                atomicAdd(red1 + j, q0);
                atomicAdd(red1 + j + 1, q1);
            }

            if (LAST) {
                if (r0 < n)
                    *reinterpret_cast<float2*>(outF + (size_t)r0 * 128 + j) =
                        make_float2(v0, v1);
                if (r1 < n)
                    *reinterpret_cast<float2*>(outF + (size_t)r1 * 128 + j) =
                        make_float2(v2, v3);
            } else {
                if (r0 < n) {
                    bf16 h0 = __float2bfloat16_rn(v0);
                    bf16 h1 = __float2bfloat16_rn(v1);
                    __nv_bfloat162 hp; hp.x = h0; hp.y = h1;
                    *reinterpret_cast<uint32_t*>(Ch + (size_t)r0 * 128 + j) =
                        *reinterpret_cast<uint32_t*>(&hp);
                    *reinterpret_cast<uint32_t*>(Cl + (size_t)r0 * 128 + j) =
                        pack2bf(v0 - __bfloat162float(h0), v1 - __bfloat162float(h1));
                }
                if (r1 < n) {
                    bf16 h2 = __float2bfloat16_rn(v2);
                    bf16 h3 = __float2bfloat16_rn(v3);
                    __nv_bfloat162 hp; hp.x = h2; hp.y = h3;
                    *reinterpret_cast<uint32_t*>(Ch + (size_t)r1 * 128 + j) =
                        *reinterpret_cast<uint32_t*>(&hp);
                    *reinterpret_cast<uint32_t*>(Cl + (size_t)r1 * 128 + j) =
                        pack2bf(v2 - __bfloat162float(h2), v3 - __bfloat162float(h3));
                }
            }
        }
    }
    __syncthreads();
    if (tid < 128) {
        atomicAdd(&stats[tid], red0[tid]);
        atomicAdd(&stats[128 + tid], red1[tid]);
    }
}

// ============================ host launcher ==================================
extern "C" void kernel_launch(void* const* d_in, const int* in_sizes, int n_in,
                              void* d_out, int out_size) {
    const float* x = (const float*)d_in[0];
    const void* ei = d_in[1];
    const float* ea = (const float*)d_in[2];
    const float* u = (const float*)d_in[3];
    const void* batch = d_in[4];
    const float* W0 = (const float*)d_in[5];
    const float* b0 = (const float*)d_in[6];
    const float* W1 = (const float*)d_in[7];
    const float* b1 = (const float*)d_in[8];
    const float* W2 = (const float*)d_in[9];
    const float* b2 = (const float*)d_in[10];
    const float* g0 = (const float*)d_in[11];
    const float* be0 = (const float*)d_in[12];
    const float* g1 = (const float*)d_in[13];
    const float* be1 = (const float*)d_in[14];
    const float* g2 = (const float*)d_in[15];
    const float* be2 = (const float*)d_in[16];

    int n = in_sizes[0] / DIM;
    int nE = in_sizes[2] / DIM;
    int nG = in_sizes[3] / DIM;
    float* out = (float*)d_out;

    bf16 *combh, *combl, *h0h, *h0l, *h1h, *h1l;
    bf16 *w0h, *w0l, *wf1h, *wf1l, *wf2h, *wf2l;
    float *stats, *bf1, *bf2, *ubias;
    cudaGetSymbolAddress((void**)&combh, g_combh);
    cudaGetSymbolAddress((void**)&combl, g_combl);
    cudaGetSymbolAddress((void**)&h0h, g_h0h);
    cudaGetSymbolAddress((void**)&h0l, g_h0l);
    cudaGetSymbolAddress((void**)&h1h, g_h1h);
    cudaGetSymbolAddress((void**)&h1l, g_h1l);
    cudaGetSymbolAddress((void**)&w0h, g_w0h);
    cudaGetSymbolAddress((void**)&w0l, g_w0l);
    cudaGetSymbolAddress((void**)&wf1h, g_wf1h);
    cudaGetSymbolAddress((void**)&wf1l, g_wf1l);
    cudaGetSymbolAddress((void**)&wf2h, g_wf2h);
    cudaGetSymbolAddress((void**)&wf2l, g_wf2l);
    cudaGetSymbolAddress((void**)&stats, g_stats);
    cudaGetSymbolAddress((void**)&bf1, g_bf1);
    cudaGetSymbolAddress((void**)&bf2, g_bf2);
    cudaGetSymbolAddress((void**)&ubias, g_ubias);

    cudaFuncSetAttribute(gemm_mma<KC0, false, true>,
                         cudaFuncAttributeMaxDynamicSharedMemorySize, GEMM_SMEM);
    cudaFuncSetAttribute(gemm_mma<DIM, false, false>,
                         cudaFuncAttributeMaxDynamicSharedMemorySize, GEMM_SMEM);
    cudaFuncSetAttribute(gemm_mma<DIM, true, false>,
                         cudaFuncAttributeMaxDynamicSharedMemorySize, GEMM_SMEM);

    int nb = (n + 1023) / 1024;  // 49 scan blocks, all resident in 148

    prep_kernel<<<256, 256>>>((const int*)ei, W0, b0, u, nG);
    hist_kernel<<<(nE + 255) / 256, 256>>>(ei, nE, n);
    scanfill_gather_kernel<<<148, 1024>>>(ei, ea, x, nE, n, nb);

    int gblocks = (n + 127) / 128;
    gemm_mma<KC0, false, true><<<gblocks, 256, GEMM_SMEM>>>(       // 4th: profiled
        combh, combl, w0h, w0l, nullptr, ubias, batch, nullptr, h0h, h0l, stats, n);
    fold_kernel<<<1, 128>>>(stats, g0, be0, W1, b1, wf1h, wf1l, bf1, (float)n);
    gemm_mma<DIM, false, false><<<gblocks, 256, GEMM_SMEM>>>(
        h0h, h0l, wf1h, wf1l, bf1, nullptr, nullptr, nullptr, h1h, h1l,
        stats + 256, n);
    fold_kernel<<<1, 128>>>(stats + 256, g1, be1, W2, b2, wf2h, wf2l, bf2, (float)n);
    gemm_mma<DIM, true, false><<<gblocks, 256, GEMM_SMEM>>>(
        h1h, h1l, wf2h, wf2l, bf2, nullptr, nullptr, out, nullptr, nullptr,
        stats + 512, n);
    finalfold_kernel<<<1, 128>>>(stats + 512, g2, be2, (float)n);
    norm_kernel<<<1024, 256>>>(out, n);
}